// round 3
// baseline (speedup 1.0000x reference)
#include <cuda_runtime.h>
#include <math.h>
#include <float.h>

#define MAXN 50000
#define MAXE 800000
#define DMAX 256

// ---------------- static device scratch ----------------
__device__ float g_q[(size_t)MAXN * DMAX];
__device__ float g_k[(size_t)MAXN * DMAX];
__device__ float g_v[(size_t)MAXN * DMAX];
__device__ float g_h1[(size_t)MAXN * DMAX];
__device__ float g_h2[(size_t)MAXN * DMAX];
__device__ float g_score[MAXE];
__device__ float g_denom[MAXN];
__device__ unsigned g_smax[MAXN];
__device__ int g_src[MAXE];
__device__ int g_dst[MAXE];
__device__ int g_is64;
__device__ float g_psum[256];
__device__ unsigned g_pmax[256];

__device__ __forceinline__ float* sel(int w) {
    switch (w) {
        case 0: return g_q;
        case 1: return g_k;
        case 2: return g_v;
        case 3: return g_h1;
        default: return g_h2;
    }
}

__device__ __forceinline__ unsigned fenc(float f) {
    unsigned u = __float_as_uint(f);
    return (u & 0x80000000u) ? ~u : (u | 0x80000000u);
}
__device__ __forceinline__ float fdec(unsigned u) {
    u = (u & 0x80000000u) ? (u ^ 0x80000000u) : ~u;
    return __uint_as_float(u);
}
#define ENC_NEG_INF 0x007FFFFFu

// ---------------- edge index width detection + conversion ----------------
__global__ void detect_kernel(const unsigned* __restrict__ ei, int E) {
    if (threadIdx.x == 0 && blockIdx.x == 0) {
        int n = E < 64 ? E : 64;
        int is64 = 1;
        for (int i = 0; i < n; i++) {
            if (ei[2 * i + 1] != 0u) { is64 = 0; break; }
        }
        g_is64 = is64;
    }
}

__global__ void convert_kernel(const void* __restrict__ ei, int E) {
    int i = blockIdx.x * blockDim.x + threadIdx.x;
    if (i >= E) return;
    if (g_is64) {
        const long long* p = (const long long*)ei;
        g_src[i] = (int)p[i];
        g_dst[i] = (int)p[E + i];
    } else {
        const int* p = (const int*)ei;
        g_src[i] = p[i];
        g_dst[i] = p[E + i];
    }
}

// ---------------- fused fp32 GEMM: 4 weights share one A ----------------
// C_w = A @ W_w + b_w  for w in 0..3, each W_w is [K, Nper].
// blockIdx.x spans 4 * (Nper/BN) column blocks.
#define BM 128
#define BN 128
#define BK 16
#define AS_STRIDE 132
#define WS_STRIDE 128

__global__ __launch_bounds__(256, 2)
void gemm4_kernel(const float* __restrict__ Aext, int a_sel,
                  const float* __restrict__ W0, const float* __restrict__ W1,
                  const float* __restrict__ W2, const float* __restrict__ W3,
                  const float* __restrict__ b0, const float* __restrict__ b1,
                  const float* __restrict__ b2, const float* __restrict__ b3,
                  int c0, int c1, int c2, int c3,
                  int M, int K, int Nper, int sanitize) {
    __shared__ float As[2][BK * AS_STRIDE];
    __shared__ float Ws[2][BK * WS_STRIDE];

    const float* A = (a_sel >= 0) ? sel(a_sel) : Aext;

    int cbPerW = Nper / BN;                 // 2 (Nper=256) or 1 (Nper=128)
    int wsel = blockIdx.x / cbPerW;
    int colBase = (blockIdx.x - wsel * cbPerW) * BN;
    const float* W;
    const float* bias;
    int csel;
    switch (wsel) {
        case 0: W = W0; bias = b0; csel = c0; break;
        case 1: W = W1; bias = b1; csel = c1; break;
        case 2: W = W2; bias = b2; csel = c2; break;
        default: W = W3; bias = b3; csel = c3; break;
    }
    float* C = sel(csel);

    int tid = threadIdx.x;                  // 256
    int tx = tid & 15;                      // N dir, 8 cols each
    int ty = tid >> 4;                      // M dir, 8 rows each
    int rowBase = blockIdx.y * BM;

    // A-load mapping: float4 f = tid + i*256 ; row = f>>2 ; kq = f&3
    int a_row0 = tid >> 2;                  // i=0: rows 0..63
    int a_kq = (tid & 3) * 4;
    // W-load mapping: float4 f = tid + i*256 ; kk = f>>5 ; nc = (f&31)*4
    int w_kk0 = tid >> 5;                   // i=0: kk 0..7
    int w_nc = (tid & 31) * 4;

    float acc[8][8];
#pragma unroll
    for (int i = 0; i < 8; i++)
#pragma unroll
        for (int j = 0; j < 8; j++) acc[i][j] = 0.f;

    float4 aReg[2], wReg[2];

    // ---- prologue: load k0 = 0 ----
    {
        int k0 = 0;
#pragma unroll
        for (int i = 0; i < 2; i++) {
            int row = a_row0 + i * 64;
            int gr = rowBase + row;
            float4 v = make_float4(0.f, 0.f, 0.f, 0.f);
            if (gr < M) v = *(const float4*)(A + (size_t)gr * K + k0 + a_kq);
            if (sanitize) {
                if (v.x != v.x) v.x = 0.f;
                if (v.y != v.y) v.y = 0.f;
                if (v.z != v.z) v.z = 0.f;
                if (v.w != v.w) v.w = 0.f;
            }
            aReg[i] = v;
            int kk = w_kk0 + i * 8;
            wReg[i] = *(const float4*)(W + (size_t)(k0 + kk) * Nper + colBase + w_nc);
        }
#pragma unroll
        for (int i = 0; i < 2; i++) {
            int row = a_row0 + i * 64;
            As[0][(a_kq + 0) * AS_STRIDE + row] = aReg[i].x;
            As[0][(a_kq + 1) * AS_STRIDE + row] = aReg[i].y;
            As[0][(a_kq + 2) * AS_STRIDE + row] = aReg[i].z;
            As[0][(a_kq + 3) * AS_STRIDE + row] = aReg[i].w;
            int kk = w_kk0 + i * 8;
            *(float4*)&Ws[0][kk * WS_STRIDE + w_nc] = wReg[i];
        }
    }
    __syncthreads();

    int buf = 0;
    for (int k0 = BK; k0 < K; k0 += BK) {
        // load next tile into registers
#pragma unroll
        for (int i = 0; i < 2; i++) {
            int row = a_row0 + i * 64;
            int gr = rowBase + row;
            float4 v = make_float4(0.f, 0.f, 0.f, 0.f);
            if (gr < M) v = *(const float4*)(A + (size_t)gr * K + k0 + a_kq);
            if (sanitize) {
                if (v.x != v.x) v.x = 0.f;
                if (v.y != v.y) v.y = 0.f;
                if (v.z != v.z) v.z = 0.f;
                if (v.w != v.w) v.w = 0.f;
            }
            aReg[i] = v;
            int kk = w_kk0 + i * 8;
            wReg[i] = *(const float4*)(W + (size_t)(k0 + kk) * Nper + colBase + w_nc);
        }
        // compute on current buffer
#pragma unroll
        for (int kk = 0; kk < BK; kk++) {
            float4 a0 = *(const float4*)&As[buf][kk * AS_STRIDE + ty * 8];
            float4 a1 = *(const float4*)&As[buf][kk * AS_STRIDE + ty * 8 + 4];
            float4 w0 = *(const float4*)&Ws[buf][kk * WS_STRIDE + tx * 8];
            float4 w1 = *(const float4*)&Ws[buf][kk * WS_STRIDE + tx * 8 + 4];
            float a[8] = {a0.x, a0.y, a0.z, a0.w, a1.x, a1.y, a1.z, a1.w};
            float w[8] = {w0.x, w0.y, w0.z, w0.w, w1.x, w1.y, w1.z, w1.w};
#pragma unroll
            for (int i = 0; i < 8; i++)
#pragma unroll
                for (int j = 0; j < 8; j++) acc[i][j] += a[i] * w[j];
        }
        // store next tile into other buffer
        int nb = buf ^ 1;
#pragma unroll
        for (int i = 0; i < 2; i++) {
            int row = a_row0 + i * 64;
            As[nb][(a_kq + 0) * AS_STRIDE + row] = aReg[i].x;
            As[nb][(a_kq + 1) * AS_STRIDE + row] = aReg[i].y;
            As[nb][(a_kq + 2) * AS_STRIDE + row] = aReg[i].z;
            As[nb][(a_kq + 3) * AS_STRIDE + row] = aReg[i].w;
            int kk = w_kk0 + i * 8;
            *(float4*)&Ws[nb][kk * WS_STRIDE + w_nc] = wReg[i];
        }
        __syncthreads();
        buf = nb;
    }

    // last tile compute
#pragma unroll
    for (int kk = 0; kk < BK; kk++) {
        float4 a0 = *(const float4*)&As[buf][kk * AS_STRIDE + ty * 8];
        float4 a1 = *(const float4*)&As[buf][kk * AS_STRIDE + ty * 8 + 4];
        float4 w0 = *(const float4*)&Ws[buf][kk * WS_STRIDE + tx * 8];
        float4 w1 = *(const float4*)&Ws[buf][kk * WS_STRIDE + tx * 8 + 4];
        float a[8] = {a0.x, a0.y, a0.z, a0.w, a1.x, a1.y, a1.z, a1.w};
        float w[8] = {w0.x, w0.y, w0.z, w0.w, w1.x, w1.y, w1.z, w1.w};
#pragma unroll
        for (int i = 0; i < 8; i++)
#pragma unroll
            for (int j = 0; j < 8; j++) acc[i][j] += a[i] * w[j];
    }

    // epilogue: bias + store
    float bb[8];
#pragma unroll
    for (int j = 0; j < 8; j++) bb[j] = bias[colBase + tx * 8 + j];
#pragma unroll
    for (int i = 0; i < 8; i++) {
        int gr = rowBase + ty * 8 + i;
        if (gr >= M) continue;
        float4 o0 = make_float4(acc[i][0] + bb[0], acc[i][1] + bb[1],
                                acc[i][2] + bb[2], acc[i][3] + bb[3]);
        float4 o1 = make_float4(acc[i][4] + bb[4], acc[i][5] + bb[5],
                                acc[i][6] + bb[6], acc[i][7] + bb[7]);
        *(float4*)(C + (size_t)gr * Nper + colBase + tx * 8) = o0;
        *(float4*)(C + (size_t)gr * Nper + colBase + tx * 8 + 4) = o1;
    }
}

// ---------------- per-node softmax-state init ----------------
__global__ void init_nodes_kernel(int Nn) {
    int i = blockIdx.x * blockDim.x + threadIdx.x;
    if (i < Nn) {
        g_smax[i] = ENC_NEG_INF;
        g_denom[i] = 0.f;
    }
}

// ---------------- edge score ----------------
__global__ void edge_score_kernel(int E, int d, float inv_sqrt_d) {
    int e = (blockIdx.x * blockDim.x + threadIdx.x) >> 5;
    int lane = threadIdx.x & 31;
    if (e >= E) return;
    int s = g_src[e], t = g_dst[e];
    const float* qr = g_q + (size_t)t * d;
    const float* kr = g_k + (size_t)s * d;
    float sum = 0.f;
    for (int j = lane * 4; j < d; j += 128) {
        float4 a = *(const float4*)(qr + j);
        float4 b = *(const float4*)(kr + j);
        sum += a.x * b.x + a.y * b.y + a.z * b.z + a.w * b.w;
    }
#pragma unroll
    for (int o = 16; o; o >>= 1) sum += __shfl_xor_sync(0xFFFFFFFFu, sum, o);
    if (lane == 0) {
        float sc = sum * inv_sqrt_d;
        g_score[e] = sc;
        atomicMax(&g_smax[t], fenc(sc));
    }
}

// ---------------- exp + denominator ----------------
__global__ void edge_exp_kernel(int E) {
    int e = blockIdx.x * blockDim.x + threadIdx.x;
    if (e >= E) return;
    int t = g_dst[e];
    float ex = expf(g_score[e] - fdec(g_smax[t]));
    g_score[e] = ex;
    atomicAdd(&g_denom[t], ex);
}

// ---------------- scatter: h[dst] += alpha * v[src] ----------------
__global__ void edge_scatter_kernel(int E, int d, int h_sel) {
    int e = (blockIdx.x * blockDim.x + threadIdx.x) >> 5;
    int lane = threadIdx.x & 31;
    if (e >= E) return;
    int s = g_src[e], t = g_dst[e];
    float alpha = g_score[e] / g_denom[t];
    const float* vr = g_v + (size_t)s * d;
    float* hr = sel(h_sel) + (size_t)t * d;
    for (int j = lane * 4; j < d; j += 128) {
        float4 a = *(const float4*)(vr + j);
        atomicAdd(&hr[j + 0], alpha * a.x);
        atomicAdd(&hr[j + 1], alpha * a.y);
        atomicAdd(&hr[j + 2], alpha * a.z);
        atomicAdd(&hr[j + 3], alpha * a.w);
    }
}

// ---------------- pooling ----------------
__global__ void pool_init_kernel() {
    int c = threadIdx.x;
    if (c < 256) {
        g_psum[c] = 0.f;
        g_pmax[c] = ENC_NEG_INF;
    }
}

__global__ void pool_kernel(int M, int d) {
    int c = threadIdx.x;
    const float* h = g_h2;
    float sum = 0.f, mx = -FLT_MAX;
    for (int r = blockIdx.x; r < M; r += gridDim.x) {
        float v = h[(size_t)r * d + c];
        sum += v;
        mx = fmaxf(mx, v);
    }
    atomicAdd(&g_psum[c], sum);
    atomicMax(&g_pmax[c], fenc(mx));
}

__global__ void pool_final_kernel(float* __restrict__ out, int M, int d) {
    int c = threadIdx.x;
    if (c < d) {
        out[c] = g_psum[c] / (float)M;
        out[d + c] = fdec(g_pmax[c]);
    }
}

// ---------------- launch ----------------
extern "C" void kernel_launch(void* const* d_in, const int* in_sizes, int n_in,
                              void* d_out, int out_size) {
    const float* x   = (const float*)d_in[0];
    const void*  ei  = d_in[1];
    const float* Wq1 = (const float*)d_in[3];
    const float* bq1 = (const float*)d_in[4];
    const float* Wk1 = (const float*)d_in[5];
    const float* bk1 = (const float*)d_in[6];
    const float* Wv1 = (const float*)d_in[7];
    const float* bv1 = (const float*)d_in[8];
    const float* Ws1 = (const float*)d_in[9];
    const float* bs1 = (const float*)d_in[10];
    const float* Wq2 = (const float*)d_in[11];
    const float* bq2 = (const float*)d_in[12];
    const float* Wk2 = (const float*)d_in[13];
    const float* bk2 = (const float*)d_in[14];
    const float* Wv2 = (const float*)d_in[15];
    const float* bv2 = (const float*)d_in[16];
    const float* Ws2 = (const float*)d_in[17];
    const float* bs2 = (const float*)d_in[18];
    float* out = (float*)d_out;

    const int D_IN = 512, D_HID = 256, D_OUT = 128;
    int Nn = in_sizes[0] / D_IN;
    int E  = in_sizes[2];

    detect_kernel<<<1, 32>>>((const unsigned*)ei, E);
    convert_kernel<<<(E + 255) / 256, 256>>>(ei, E);

    int gy = (Nn + BM - 1) / BM;

    // ===== layer 1: fused 4-way GEMM (K=512, Nper=256) =====
    {
        dim3 g(4 * (D_HID / BN), gy);
        gemm4_kernel<<<g, 256>>>(x, -1, Wq1, Wk1, Wv1, Ws1, bq1, bk1, bv1, bs1,
                                 0, 1, 2, 3, Nn, D_IN, D_HID, 1);
    }
    init_nodes_kernel<<<(Nn + 255) / 256, 256>>>(Nn);
    {
        float inv = (float)(1.0 / sqrt((double)D_HID));
        int blks = (E + 7) / 8;
        edge_score_kernel<<<blks, 256>>>(E, D_HID, inv);
        edge_exp_kernel<<<(E + 255) / 256, 256>>>(E);
        edge_scatter_kernel<<<blks, 256>>>(E, D_HID, 3);
    }

    // ===== layer 2: fused 4-way GEMM (K=256, Nper=128) =====
    {
        dim3 g(4 * (D_OUT / BN), gy);
        gemm4_kernel<<<g, 256>>>(nullptr, 3, Wq2, Wk2, Wv2, Ws2, bq2, bk2, bv2, bs2,
                                 0, 1, 2, 4, Nn, D_HID, D_OUT, 0);
    }
    init_nodes_kernel<<<(Nn + 255) / 256, 256>>>(Nn);
    {
        float inv = (float)(1.0 / sqrt((double)D_OUT));
        int blks = (E + 7) / 8;
        edge_score_kernel<<<blks, 256>>>(E, D_OUT, inv);
        edge_exp_kernel<<<(E + 255) / 256, 256>>>(E);
        edge_scatter_kernel<<<blks, 256>>>(E, D_OUT, 4);
    }

    // ===== pooling =====
    pool_init_kernel<<<1, 256>>>();
    pool_kernel<<<256, D_OUT>>>(Nn, D_OUT);
    pool_final_kernel<<<1, 256>>>(out, Nn, D_OUT);
}

// round 5
// speedup vs baseline: 1.8073x; 1.8073x over previous
#include <cuda_runtime.h>
#include <cuda_bf16.h>
#include <math.h>
#include <float.h>
#include <stdint.h>

#define MAXN 50000
#define MAXE 800000
#define DMAX 256

// ---------------- static device scratch ----------------
__device__ float g_q[(size_t)MAXN * DMAX];
__device__ float g_k[(size_t)MAXN * DMAX];
__device__ float g_v[(size_t)MAXN * DMAX];
__device__ float g_h1[(size_t)MAXN * DMAX];
__device__ float g_h2[(size_t)MAXN * DMAX];
__device__ float g_score[MAXE];
__device__ float g_denom[MAXN];
__device__ unsigned g_smax[MAXN];
__device__ int g_src[MAXE];
__device__ int g_dst[MAXE];
__device__ int g_is64;
__device__ float g_psum[256];
__device__ unsigned g_pmax[256];

__device__ __forceinline__ float* sel(int w) {
    switch (w) {
        case 0: return g_q;
        case 1: return g_k;
        case 2: return g_v;
        case 3: return g_h1;
        default: return g_h2;
    }
}

__device__ __forceinline__ unsigned fenc(float f) {
    unsigned u = __float_as_uint(f);
    return (u & 0x80000000u) ? ~u : (u | 0x80000000u);
}
__device__ __forceinline__ float fdec(unsigned u) {
    u = (u & 0x80000000u) ? (u ^ 0x80000000u) : ~u;
    return __uint_as_float(u);
}
#define ENC_NEG_INF 0x007FFFFFu

// ---------------- PTX helpers (sm_80-era, safe for plain sm_103 target) ----------------
__device__ __forceinline__ uint32_t smem_u32(const void* p) {
    uint32_t a;
    asm("{ .reg .u64 t; cvta.to.shared.u64 t, %1; cvt.u32.u64 %0, t; }" : "=r"(a) : "l"(p));
    return a;
}

__device__ __forceinline__ void ldm_x4(uint32_t& r0, uint32_t& r1, uint32_t& r2, uint32_t& r3,
                                       uint32_t addr) {
    asm volatile("ldmatrix.sync.aligned.m8n8.x4.shared.b16 {%0,%1,%2,%3}, [%4];"
        : "=r"(r0), "=r"(r1), "=r"(r2), "=r"(r3) : "r"(addr));
}

__device__ __forceinline__ void mma_bf16(float* c, const uint32_t* a, const uint32_t* b) {
    asm volatile("mma.sync.aligned.m16n8k16.row.col.f32.bf16.bf16.f32 "
        "{%0,%1,%2,%3}, {%4,%5,%6,%7}, {%8,%9}, {%0,%1,%2,%3};"
        : "+f"(c[0]), "+f"(c[1]), "+f"(c[2]), "+f"(c[3])
        : "r"(a[0]), "r"(a[1]), "r"(a[2]), "r"(a[3]), "r"(b[0]), "r"(b[1]));
}

// pack two floats -> bf16x2 word (lo half = first arg)
__device__ __forceinline__ uint32_t pack_bf(float a, float b) {
    __nv_bfloat162 t = __floats2bfloat162_rn(a, b);
    return *(uint32_t*)&t;
}
__device__ __forceinline__ float bf_hi_val(float v, float& lo) {
    __nv_bfloat16 h = __float2bfloat16_rn(v);
    float hf = __bfloat162float(h);
    lo = v - hf;
    return hf;
}

// ---------------- edge index width detection + conversion ----------------
__global__ void detect_kernel(const unsigned* __restrict__ ei, int E) {
    if (threadIdx.x == 0 && blockIdx.x == 0) {
        int n = E < 64 ? E : 64;
        int is64 = 1;
        for (int i = 0; i < n; i++) {
            if (ei[2 * i + 1] != 0u) { is64 = 0; break; }
        }
        g_is64 = is64;
    }
}

__global__ void convert_kernel(const void* __restrict__ ei, int E) {
    int i = blockIdx.x * blockDim.x + threadIdx.x;
    if (i >= E) return;
    if (g_is64) {
        const long long* p = (const long long*)ei;
        g_src[i] = (int)p[i];
        g_dst[i] = (int)p[E + i];
    } else {
        const int* p = (const int*)ei;
        g_src[i] = p[i];
        g_dst[i] = p[E + i];
    }
}

// ================= bf16 mma.sync GEMM (3xBF16 compensated) =================
// C_w = A @ W_w + b_w.  A: [M,K] fp32 row-major.  W_w: [K,Nt] fp32 row-major.
// Block tile 128(M) x 128(N), K-chunk 32. 8 warps: wm = wid&1 (64 rows), wn = wid>>1 (32 cols).
// Smem per buffer: A_hi/A_lo [128][40] bf16, B_hi/B_lo [128 n][40 k] bf16 (80B padded rows).
#define SM_ST 40           // padded row stride in bf16 elements (80 bytes)
#define OFF_AH 0
#define OFF_AL 10240
#define OFF_BH 20480
#define OFF_BL 30720
#define BUF_SZ 40960
#define GEMM_SMEM (2 * BUF_SZ)

__global__ __launch_bounds__(256, 1)
void gemm_mma_kernel(const float* __restrict__ Aext, int a_sel,
                     const float* __restrict__ W0, const float* __restrict__ W1,
                     const float* __restrict__ W2, const float* __restrict__ W3,
                     const float* __restrict__ b0, const float* __restrict__ b1,
                     const float* __restrict__ b2, const float* __restrict__ b3,
                     int c0, int c1, int c2, int c3,
                     int M, int K, int Nt, int sanitize) {
    extern __shared__ char smem[];
    const uint32_t sbase = smem_u32(smem);

    const int tid = threadIdx.x;
    const int wid = tid >> 5;
    const int lid = tid & 31;
    const int wm = wid & 1;        // M half
    const int wn = wid >> 1;       // N quarter
    const int rowBase = blockIdx.y * 128;

    const int cbPerW = Nt >> 7;    // 128-col blocks per weight
    const int wsel = blockIdx.x / cbPerW;
    const int colBase = (blockIdx.x - wsel * cbPerW) * 128;

    const float* A = (a_sel >= 0) ? sel(a_sel) : Aext;
    const float* W;
    const float* bias;
    int csel;
    switch (wsel) {
        case 0: W = W0; bias = b0; csel = c0; break;
        case 1: W = W1; bias = b1; csel = c1; break;
        case 2: W = W2; bias = b2; csel = c2; break;
        default: W = W3; bias = b3; csel = c3; break;
    }
    float* C = sel(csel);

    // accumulators: 4 m-frags x 4 n-frags x 4 floats
    float acc[4][4][4];
#pragma unroll
    for (int i = 0; i < 4; i++)
#pragma unroll
        for (int j = 0; j < 4; j++)
#pragma unroll
            for (int q = 0; q < 4; q++) acc[i][j][q] = 0.f;

    // load-task mappings
    const int a_row = tid >> 3;          // + i*32 rows per iter (idx = tid + i*256)
    const int a_kq = tid & 7;            // float4 index within 32-k chunk
    const int w_n = tid & 127;           // n within block
    const int w_kp0 = tid >> 7;          // + i*2 k-pairs

    float4 aV[4];
    float wv0[8], wv1[8];

    const int nChunks = K >> 5;

    // ---- prefetch chunk 0 ----
    {
        const int k0 = 0;
#pragma unroll
        for (int i = 0; i < 4; i++) {
            int row = a_row + i * 32;
            int gr = rowBase + row;
            float4 v = make_float4(0.f, 0.f, 0.f, 0.f);
            if (gr < M) v = *(const float4*)(A + (size_t)gr * K + k0 + a_kq * 4);
            if (sanitize) {
                if (v.x != v.x) v.x = 0.f;
                if (v.y != v.y) v.y = 0.f;
                if (v.z != v.z) v.z = 0.f;
                if (v.w != v.w) v.w = 0.f;
            }
            aV[i] = v;
        }
#pragma unroll
        for (int i = 0; i < 8; i++) {
            int kp = w_kp0 + i * 2;
            wv0[i] = W[(size_t)(k0 + kp * 2) * Nt + colBase + w_n];
            wv1[i] = W[(size_t)(k0 + kp * 2 + 1) * Nt + colBase + w_n];
        }
    }

    int buf = 0;
    for (int c = 0; c < nChunks; c++) {
        // ---- store prefetched chunk into buffer `buf` ----
        uint32_t bb = sbase + buf * BUF_SZ;
#pragma unroll
        for (int i = 0; i < 4; i++) {
            int row = a_row + i * 32;
            float lox, loy, loz, low;
            float hx = bf_hi_val(aV[i].x, lox);
            float hy = bf_hi_val(aV[i].y, loy);
            float hz = bf_hi_val(aV[i].z, loz);
            float hw = bf_hi_val(aV[i].w, low);
            uint2 hi = make_uint2(pack_bf(hx, hy), pack_bf(hz, hw));
            uint2 lo = make_uint2(pack_bf(lox, loy), pack_bf(loz, low));
            uint32_t off = (uint32_t)(row * 80 + a_kq * 8);
            *(uint2*)(smem + (buf * BUF_SZ + OFF_AH) + off) = hi;
            *(uint2*)(smem + (buf * BUF_SZ + OFF_AL) + off) = lo;
        }
#pragma unroll
        for (int i = 0; i < 8; i++) {
            int kp = w_kp0 + i * 2;
            float lo0, lo1;
            float h0 = bf_hi_val(wv0[i], lo0);
            float h1 = bf_hi_val(wv1[i], lo1);
            uint32_t off = (uint32_t)(w_n * 80 + kp * 4);
            *(uint32_t*)(smem + (buf * BUF_SZ + OFF_BH) + off) = pack_bf(h0, h1);
            *(uint32_t*)(smem + (buf * BUF_SZ + OFF_BL) + off) = pack_bf(lo0, lo1);
        }
        __syncthreads();

        // ---- prefetch next chunk ----
        if (c + 1 < nChunks) {
            const int k0 = (c + 1) << 5;
#pragma unroll
            for (int i = 0; i < 4; i++) {
                int row = a_row + i * 32;
                int gr = rowBase + row;
                float4 v = make_float4(0.f, 0.f, 0.f, 0.f);
                if (gr < M) v = *(const float4*)(A + (size_t)gr * K + k0 + a_kq * 4);
                if (sanitize) {
                    if (v.x != v.x) v.x = 0.f;
                    if (v.y != v.y) v.y = 0.f;
                    if (v.z != v.z) v.z = 0.f;
                    if (v.w != v.w) v.w = 0.f;
                }
                aV[i] = v;
            }
#pragma unroll
            for (int i = 0; i < 8; i++) {
                int kp = w_kp0 + i * 2;
                wv0[i] = W[(size_t)(k0 + kp * 2) * Nt + colBase + w_n];
                wv1[i] = W[(size_t)(k0 + kp * 2 + 1) * Nt + colBase + w_n];
            }
        }

        // ---- MMA over current buffer: 2 k16 steps ----
        const int lr = lid & 15;
        const int lc = lid >> 4;
        uint32_t AHB = bb + OFF_AH, ALB = bb + OFF_AL;
        uint32_t BHB = bb + OFF_BH, BLB = bb + OFF_BL;
#pragma unroll
        for (int ks = 0; ks < 2; ks++) {
            uint32_t koff = (uint32_t)(ks * 32 + lc * 16);
            uint32_t ah[4][4], al[4][4], bh[4][2], bl[4][2];
#pragma unroll
            for (int i = 0; i < 4; i++) {
                uint32_t ro = (uint32_t)((wm * 64 + i * 16 + lr) * 80) + koff;
                ldm_x4(ah[i][0], ah[i][1], ah[i][2], ah[i][3], AHB + ro);
                ldm_x4(al[i][0], al[i][1], al[i][2], al[i][3], ALB + ro);
            }
#pragma unroll
            for (int j2 = 0; j2 < 2; j2++) {
                uint32_t ro = (uint32_t)((wn * 32 + j2 * 16 + lr) * 80) + koff;
                uint32_t r0, r1, r2, r3;
                ldm_x4(r0, r1, r2, r3, BHB + ro);
                bh[j2 * 2 + 0][0] = r0; bh[j2 * 2 + 0][1] = r2;
                bh[j2 * 2 + 1][0] = r1; bh[j2 * 2 + 1][1] = r3;
                ldm_x4(r0, r1, r2, r3, BLB + ro);
                bl[j2 * 2 + 0][0] = r0; bl[j2 * 2 + 0][1] = r2;
                bl[j2 * 2 + 1][0] = r1; bl[j2 * 2 + 1][1] = r3;
            }
#pragma unroll
            for (int i = 0; i < 4; i++)
#pragma unroll
                for (int j = 0; j < 4; j++) {
                    mma_bf16(acc[i][j], ah[i], bh[j]);
                    mma_bf16(acc[i][j], ah[i], bl[j]);
                    mma_bf16(acc[i][j], al[i], bh[j]);
                }
        }
        __syncthreads();
        buf ^= 1;
    }

    // ---- epilogue: bias + store ----
    const int lr4 = lid >> 2;       // 0..7
    const int lc2 = (lid & 3) * 2;  // 0,2,4,6
#pragma unroll
    for (int j = 0; j < 4; j++) {
        int gc = colBase + wn * 32 + j * 8 + lc2;
        float bi0 = bias[gc], bi1 = bias[gc + 1];
#pragma unroll
        for (int i = 0; i < 4; i++) {
            int gr0 = rowBase + wm * 64 + i * 16 + lr4;
            int gr1 = gr0 + 8;
            if (gr0 < M) {
                float2 o = make_float2(acc[i][j][0] + bi0, acc[i][j][1] + bi1);
                *(float2*)(C + (size_t)gr0 * Nt + gc) = o;
            }
            if (gr1 < M) {
                float2 o = make_float2(acc[i][j][2] + bi0, acc[i][j][3] + bi1);
                *(float2*)(C + (size_t)gr1 * Nt + gc) = o;
            }
        }
    }
}

// ---------------- per-node softmax-state init ----------------
__global__ void init_nodes_kernel(int Nn) {
    int i = blockIdx.x * blockDim.x + threadIdx.x;
    if (i < Nn) {
        g_smax[i] = ENC_NEG_INF;
        g_denom[i] = 0.f;
    }
}

// ---------------- edge score ----------------
__global__ void edge_score_kernel(int E, int d, float inv_sqrt_d) {
    int e = (blockIdx.x * blockDim.x + threadIdx.x) >> 5;
    int lane = threadIdx.x & 31;
    if (e >= E) return;
    int s = g_src[e], t = g_dst[e];
    const float* qr = g_q + (size_t)t * d;
    const float* kr = g_k + (size_t)s * d;
    float sum = 0.f;
    for (int j = lane * 4; j < d; j += 128) {
        float4 a = *(const float4*)(qr + j);
        float4 b = *(const float4*)(kr + j);
        sum += a.x * b.x + a.y * b.y + a.z * b.z + a.w * b.w;
    }
#pragma unroll
    for (int o = 16; o; o >>= 1) sum += __shfl_xor_sync(0xFFFFFFFFu, sum, o);
    if (lane == 0) {
        float sc = sum * inv_sqrt_d;
        g_score[e] = sc;
        atomicMax(&g_smax[t], fenc(sc));
    }
}

// ---------------- exp + denominator ----------------
__global__ void edge_exp_kernel(int E) {
    int e = blockIdx.x * blockDim.x + threadIdx.x;
    if (e >= E) return;
    int t = g_dst[e];
    float ex = expf(g_score[e] - fdec(g_smax[t]));
    g_score[e] = ex;
    atomicAdd(&g_denom[t], ex);
}

// ---------------- scatter: h[dst] += alpha * v[src] ----------------
__global__ void edge_scatter_kernel(int E, int d, int h_sel) {
    int e = (blockIdx.x * blockDim.x + threadIdx.x) >> 5;
    int lane = threadIdx.x & 31;
    if (e >= E) return;
    int s = g_src[e], t = g_dst[e];
    float alpha = g_score[e] / g_denom[t];
    const float* vr = g_v + (size_t)s * d;
    float* hr = sel(h_sel) + (size_t)t * d;
    for (int j = lane * 4; j < d; j += 128) {
        float4 a = *(const float4*)(vr + j);
        atomicAdd(&hr[j + 0], alpha * a.x);
        atomicAdd(&hr[j + 1], alpha * a.y);
        atomicAdd(&hr[j + 2], alpha * a.z);
        atomicAdd(&hr[j + 3], alpha * a.w);
    }
}

// ---------------- pooling ----------------
__global__ void pool_init_kernel() {
    int c = threadIdx.x;
    if (c < 256) {
        g_psum[c] = 0.f;
        g_pmax[c] = ENC_NEG_INF;
    }
}

__global__ void pool_kernel(int M, int d) {
    int c = threadIdx.x;
    const float* h = g_h2;
    float sum = 0.f, mx = -FLT_MAX;
    for (int r = blockIdx.x; r < M; r += gridDim.x) {
        float v = h[(size_t)r * d + c];
        sum += v;
        mx = fmaxf(mx, v);
    }
    atomicAdd(&g_psum[c], sum);
    atomicMax(&g_pmax[c], fenc(mx));
}

__global__ void pool_final_kernel(float* __restrict__ out, int M, int d) {
    int c = threadIdx.x;
    if (c < d) {
        out[c] = g_psum[c] / (float)M;
        out[d + c] = fdec(g_pmax[c]);
    }
}

// ---------------- launch ----------------
extern "C" void kernel_launch(void* const* d_in, const int* in_sizes, int n_in,
                              void* d_out, int out_size) {
    const float* x   = (const float*)d_in[0];
    const void*  ei  = d_in[1];
    const float* Wq1 = (const float*)d_in[3];
    const float* bq1 = (const float*)d_in[4];
    const float* Wk1 = (const float*)d_in[5];
    const float* bk1 = (const float*)d_in[6];
    const float* Wv1 = (const float*)d_in[7];
    const float* bv1 = (const float*)d_in[8];
    const float* Ws1 = (const float*)d_in[9];
    const float* bs1 = (const float*)d_in[10];
    const float* Wq2 = (const float*)d_in[11];
    const float* bq2 = (const float*)d_in[12];
    const float* Wk2 = (const float*)d_in[13];
    const float* bk2 = (const float*)d_in[14];
    const float* Wv2 = (const float*)d_in[15];
    const float* bv2 = (const float*)d_in[16];
    const float* Ws2 = (const float*)d_in[17];
    const float* bs2 = (const float*)d_in[18];
    float* out = (float*)d_out;

    const int D_IN = 512, D_HID = 256, D_OUT = 128;
    int Nn = in_sizes[0] / D_IN;
    int E  = in_sizes[2];

    static int smem_set = 0;
    if (!smem_set) {
        cudaFuncSetAttribute(gemm_mma_kernel,
                             cudaFuncAttributeMaxDynamicSharedMemorySize, GEMM_SMEM);
        smem_set = 1;
    }

    detect_kernel<<<1, 32>>>((const unsigned*)ei, E);
    convert_kernel<<<(E + 255) / 256, 256>>>(ei, E);

    int nTiles = (Nn + 127) / 128;

    // ===== layer 1: K=512, Nt=256, 4 weights -> 8 column blocks =====
    {
        dim3 g(8, nTiles);
        gemm_mma_kernel<<<g, 256, GEMM_SMEM>>>(
            x, -1, Wq1, Wk1, Wv1, Ws1, bq1, bk1, bv1, bs1,
            0, 1, 2, 3, Nn, D_IN, D_HID, 1);
    }
    init_nodes_kernel<<<(Nn + 255) / 256, 256>>>(Nn);
    {
        float inv = (float)(1.0 / sqrt((double)D_HID));
        int blks = (E + 7) / 8;
        edge_score_kernel<<<blks, 256>>>(E, D_HID, inv);
        edge_exp_kernel<<<(E + 255) / 256, 256>>>(E);
        edge_scatter_kernel<<<blks, 256>>>(E, D_HID, 3);
    }

    // ===== layer 2: K=256, Nt=128, 4 weights -> 4 column blocks =====
    {
        dim3 g(4, nTiles);
        gemm_mma_kernel<<<g, 256, GEMM_SMEM>>>(
            nullptr, 3, Wq2, Wk2, Wv2, Ws2, bq2, bk2, bv2, bs2,
            0, 1, 2, 4, Nn, D_HID, D_OUT, 0);
    }
    init_nodes_kernel<<<(Nn + 255) / 256, 256>>>(Nn);
    {
        float inv = (float)(1.0 / sqrt((double)D_OUT));
        int blks = (E + 7) / 8;
        edge_score_kernel<<<blks, 256>>>(E, D_OUT, inv);
        edge_exp_kernel<<<(E + 255) / 256, 256>>>(E);
        edge_scatter_kernel<<<blks, 256>>>(E, D_OUT, 4);
    }

    // ===== pooling =====
    pool_init_kernel<<<1, 256>>>();
    pool_kernel<<<256, D_OUT>>>(Nn, D_OUT);
    pool_final_kernel<<<1, 256>>>(out, Nn, D_OUT);
}

// round 6
// speedup vs baseline: 2.4845x; 1.3746x over previous
#include <cuda_runtime.h>
#include <cuda_bf16.h>
#include <math.h>
#include <float.h>
#include <stdint.h>

#define MAXN 50000
#define MAXE 800000
#define DMAX 256
#define DEG_CAP 64

// ---------------- static device scratch ----------------
__device__ float g_q[(size_t)MAXN * DMAX];
__device__ float g_k[(size_t)MAXN * DMAX];
__device__ float g_v[(size_t)MAXN * DMAX];
__device__ float g_h1[(size_t)MAXN * DMAX];
__device__ float g_h2[(size_t)MAXN * DMAX];
__device__ float g_score[MAXE];      // spill for deg > DEG_CAP
__device__ int g_src[MAXE];
__device__ int g_dst[MAXE];
__device__ int g_ssrc[MAXE];         // src sorted by dst
__device__ int g_deg[MAXN];
__device__ int g_off[MAXN + 1];
__device__ int g_cursor[MAXN];
__device__ int g_is64;
__device__ float g_psum[256];
__device__ unsigned g_pmax[256];

__device__ __forceinline__ float* sel(int w) {
    switch (w) {
        case 0: return g_q;
        case 1: return g_k;
        case 2: return g_v;
        case 3: return g_h1;
        default: return g_h2;
    }
}

__device__ __forceinline__ unsigned fenc(float f) {
    unsigned u = __float_as_uint(f);
    return (u & 0x80000000u) ? ~u : (u | 0x80000000u);
}
__device__ __forceinline__ float fdec(unsigned u) {
    u = (u & 0x80000000u) ? (u ^ 0x80000000u) : ~u;
    return __uint_as_float(u);
}
#define ENC_NEG_INF 0x007FFFFFu

// ---------------- PTX helpers ----------------
__device__ __forceinline__ uint32_t smem_u32(const void* p) {
    uint32_t a;
    asm("{ .reg .u64 t; cvta.to.shared.u64 t, %1; cvt.u32.u64 %0, t; }" : "=r"(a) : "l"(p));
    return a;
}

__device__ __forceinline__ void ldm_x4(uint32_t& r0, uint32_t& r1, uint32_t& r2, uint32_t& r3,
                                       uint32_t addr) {
    asm volatile("ldmatrix.sync.aligned.m8n8.x4.shared.b16 {%0,%1,%2,%3}, [%4];"
        : "=r"(r0), "=r"(r1), "=r"(r2), "=r"(r3) : "r"(addr));
}

__device__ __forceinline__ void mma_bf16(float* c, const uint32_t* a, const uint32_t* b) {
    asm volatile("mma.sync.aligned.m16n8k16.row.col.f32.bf16.bf16.f32 "
        "{%0,%1,%2,%3}, {%4,%5,%6,%7}, {%8,%9}, {%0,%1,%2,%3};"
        : "+f"(c[0]), "+f"(c[1]), "+f"(c[2]), "+f"(c[3])
        : "r"(a[0]), "r"(a[1]), "r"(a[2]), "r"(a[3]), "r"(b[0]), "r"(b[1]));
}

__device__ __forceinline__ uint32_t pack_bf(float a, float b) {
    __nv_bfloat162 t = __floats2bfloat162_rn(a, b);
    return *(uint32_t*)&t;
}
__device__ __forceinline__ float bf_hi_val(float v, float& lo) {
    __nv_bfloat16 h = __float2bfloat16_rn(v);
    float hf = __bfloat162float(h);
    lo = v - hf;
    return hf;
}

// ---------------- graph preprocessing ----------------
__global__ void detect_kernel(const unsigned* __restrict__ ei, int E) {
    if (threadIdx.x == 0 && blockIdx.x == 0) {
        int n = E < 64 ? E : 64;
        int is64 = 1;
        for (int i = 0; i < n; i++) {
            if (ei[2 * i + 1] != 0u) { is64 = 0; break; }
        }
        g_is64 = is64;
    }
}

__global__ void zero_deg_kernel(int Nn) {
    int i = blockIdx.x * blockDim.x + threadIdx.x;
    if (i < Nn) g_deg[i] = 0;
}

// convert + histogram fused
__global__ void convert_kernel(const void* __restrict__ ei, int E) {
    int i = blockIdx.x * blockDim.x + threadIdx.x;
    if (i >= E) return;
    int s, t;
    if (g_is64) {
        const long long* p = (const long long*)ei;
        s = (int)p[i];
        t = (int)p[E + i];
    } else {
        const int* p = (const int*)ei;
        s = p[i];
        t = p[E + i];
    }
    g_src[i] = s;
    g_dst[i] = t;
    atomicAdd(&g_deg[t], 1);
}

// exclusive prefix sum over degrees (single block of 1024)
__global__ void scan_kernel(int Nn) {
    __shared__ int sums[1024];
    int tid = threadIdx.x;
    int chunk = (Nn + 1023) / 1024;
    int start = tid * chunk;
    int stop = start + chunk; if (stop > Nn) stop = Nn;
    int s = 0;
    for (int i = start; i < stop; i++) s += g_deg[i];
    sums[tid] = s;
    __syncthreads();
    for (int off = 1; off < 1024; off <<= 1) {
        int v = (tid >= off) ? sums[tid - off] : 0;
        __syncthreads();
        sums[tid] += v;
        __syncthreads();
    }
    int base = (tid > 0) ? sums[tid - 1] : 0;
    for (int i = start; i < stop; i++) {
        g_off[i] = base;
        g_cursor[i] = base;
        base += g_deg[i];
    }
    if (tid == 1023) g_off[Nn] = sums[1023];
}

__global__ void permute_kernel(int E) {
    int i = blockIdx.x * blockDim.x + threadIdx.x;
    if (i >= E) return;
    int t = g_dst[i];
    int pos = atomicAdd(&g_cursor[t], 1);
    g_ssrc[pos] = g_src[i];
}

// ================= bf16 mma.sync GEMM (3xBF16 compensated) =================
#define OFF_AH 0
#define OFF_AL 10240
#define OFF_BH 20480
#define OFF_BL 30720
#define BUF_SZ 40960
#define GEMM_SMEM (2 * BUF_SZ)

__global__ __launch_bounds__(256, 1)
void gemm_mma_kernel(const float* __restrict__ Aext, int a_sel,
                     const float* __restrict__ W0, const float* __restrict__ W1,
                     const float* __restrict__ W2, const float* __restrict__ W3,
                     const float* __restrict__ b0, const float* __restrict__ b1,
                     const float* __restrict__ b2, const float* __restrict__ b3,
                     int c0, int c1, int c2, int c3,
                     int M, int K, int Nt, int sanitize) {
    extern __shared__ char smem[];
    const uint32_t sbase = smem_u32(smem);

    const int tid = threadIdx.x;
    const int wid = tid >> 5;
    const int lid = tid & 31;
    const int wm = wid & 1;
    const int wn = wid >> 1;
    const int rowBase = blockIdx.y * 128;

    const int cbPerW = Nt >> 7;
    const int wsel = blockIdx.x / cbPerW;
    const int colBase = (blockIdx.x - wsel * cbPerW) * 128;

    const float* A = (a_sel >= 0) ? sel(a_sel) : Aext;
    const float* W;
    const float* bias;
    int csel;
    switch (wsel) {
        case 0: W = W0; bias = b0; csel = c0; break;
        case 1: W = W1; bias = b1; csel = c1; break;
        case 2: W = W2; bias = b2; csel = c2; break;
        default: W = W3; bias = b3; csel = c3; break;
    }
    float* C = sel(csel);

    float acc[4][4][4];
#pragma unroll
    for (int i = 0; i < 4; i++)
#pragma unroll
        for (int j = 0; j < 4; j++)
#pragma unroll
            for (int q = 0; q < 4; q++) acc[i][j][q] = 0.f;

    const int a_row = tid >> 3;
    const int a_kq = tid & 7;
    const int w_n = tid & 127;
    const int w_kp0 = tid >> 7;

    float4 aV[4];
    float wv0[8], wv1[8];

    const int nChunks = K >> 5;

    {
        const int k0 = 0;
#pragma unroll
        for (int i = 0; i < 4; i++) {
            int row = a_row + i * 32;
            int gr = rowBase + row;
            float4 v = make_float4(0.f, 0.f, 0.f, 0.f);
            if (gr < M) v = *(const float4*)(A + (size_t)gr * K + k0 + a_kq * 4);
            if (sanitize) {
                if (v.x != v.x) v.x = 0.f;
                if (v.y != v.y) v.y = 0.f;
                if (v.z != v.z) v.z = 0.f;
                if (v.w != v.w) v.w = 0.f;
            }
            aV[i] = v;
        }
#pragma unroll
        for (int i = 0; i < 8; i++) {
            int kp = w_kp0 + i * 2;
            wv0[i] = W[(size_t)(k0 + kp * 2) * Nt + colBase + w_n];
            wv1[i] = W[(size_t)(k0 + kp * 2 + 1) * Nt + colBase + w_n];
        }
    }

    int buf = 0;
    for (int c = 0; c < nChunks; c++) {
        uint32_t bb = sbase + buf * BUF_SZ;
#pragma unroll
        for (int i = 0; i < 4; i++) {
            int row = a_row + i * 32;
            float lox, loy, loz, low;
            float hx = bf_hi_val(aV[i].x, lox);
            float hy = bf_hi_val(aV[i].y, loy);
            float hz = bf_hi_val(aV[i].z, loz);
            float hw = bf_hi_val(aV[i].w, low);
            uint2 hi = make_uint2(pack_bf(hx, hy), pack_bf(hz, hw));
            uint2 lo = make_uint2(pack_bf(lox, loy), pack_bf(loz, low));
            uint32_t off = (uint32_t)(row * 80 + a_kq * 8);
            *(uint2*)(smem + (buf * BUF_SZ + OFF_AH) + off) = hi;
            *(uint2*)(smem + (buf * BUF_SZ + OFF_AL) + off) = lo;
        }
#pragma unroll
        for (int i = 0; i < 8; i++) {
            int kp = w_kp0 + i * 2;
            float lo0, lo1;
            float h0 = bf_hi_val(wv0[i], lo0);
            float h1 = bf_hi_val(wv1[i], lo1);
            uint32_t off = (uint32_t)(w_n * 80 + kp * 4);
            *(uint32_t*)(smem + (buf * BUF_SZ + OFF_BH) + off) = pack_bf(h0, h1);
            *(uint32_t*)(smem + (buf * BUF_SZ + OFF_BL) + off) = pack_bf(lo0, lo1);
        }
        __syncthreads();

        if (c + 1 < nChunks) {
            const int k0 = (c + 1) << 5;
#pragma unroll
            for (int i = 0; i < 4; i++) {
                int row = a_row + i * 32;
                int gr = rowBase + row;
                float4 v = make_float4(0.f, 0.f, 0.f, 0.f);
                if (gr < M) v = *(const float4*)(A + (size_t)gr * K + k0 + a_kq * 4);
                if (sanitize) {
                    if (v.x != v.x) v.x = 0.f;
                    if (v.y != v.y) v.y = 0.f;
                    if (v.z != v.z) v.z = 0.f;
                    if (v.w != v.w) v.w = 0.f;
                }
                aV[i] = v;
            }
#pragma unroll
            for (int i = 0; i < 8; i++) {
                int kp = w_kp0 + i * 2;
                wv0[i] = W[(size_t)(k0 + kp * 2) * Nt + colBase + w_n];
                wv1[i] = W[(size_t)(k0 + kp * 2 + 1) * Nt + colBase + w_n];
            }
        }

        const int lr = lid & 15;
        const int lc = lid >> 4;
        uint32_t AHB = bb + OFF_AH, ALB = bb + OFF_AL;
        uint32_t BHB = bb + OFF_BH, BLB = bb + OFF_BL;
#pragma unroll
        for (int ks = 0; ks < 2; ks++) {
            uint32_t koff = (uint32_t)(ks * 32 + lc * 16);
            uint32_t ah[4][4], al[4][4], bh[4][2], bl[4][2];
#pragma unroll
            for (int i = 0; i < 4; i++) {
                uint32_t ro = (uint32_t)((wm * 64 + i * 16 + lr) * 80) + koff;
                ldm_x4(ah[i][0], ah[i][1], ah[i][2], ah[i][3], AHB + ro);
                ldm_x4(al[i][0], al[i][1], al[i][2], al[i][3], ALB + ro);
            }
#pragma unroll
            for (int j2 = 0; j2 < 2; j2++) {
                uint32_t ro = (uint32_t)((wn * 32 + j2 * 16 + lr) * 80) + koff;
                uint32_t r0, r1, r2, r3;
                ldm_x4(r0, r1, r2, r3, BHB + ro);
                bh[j2 * 2 + 0][0] = r0; bh[j2 * 2 + 0][1] = r2;
                bh[j2 * 2 + 1][0] = r1; bh[j2 * 2 + 1][1] = r3;
                ldm_x4(r0, r1, r2, r3, BLB + ro);
                bl[j2 * 2 + 0][0] = r0; bl[j2 * 2 + 0][1] = r2;
                bl[j2 * 2 + 1][0] = r1; bl[j2 * 2 + 1][1] = r3;
            }
#pragma unroll
            for (int i = 0; i < 4; i++)
#pragma unroll
                for (int j = 0; j < 4; j++) {
                    mma_bf16(acc[i][j], ah[i], bh[j]);
                    mma_bf16(acc[i][j], ah[i], bl[j]);
                    mma_bf16(acc[i][j], al[i], bh[j]);
                }
        }
        __syncthreads();
        buf ^= 1;
    }

    const int lr4 = lid >> 2;
    const int lc2 = (lid & 3) * 2;
#pragma unroll
    for (int j = 0; j < 4; j++) {
        int gc = colBase + wn * 32 + j * 8 + lc2;
        float bi0 = bias[gc], bi1 = bias[gc + 1];
#pragma unroll
        for (int i = 0; i < 4; i++) {
            int gr0 = rowBase + wm * 64 + i * 16 + lr4;
            int gr1 = gr0 + 8;
            if (gr0 < M) {
                float2 o = make_float2(acc[i][j][0] + bi0, acc[i][j][1] + bi1);
                *(float2*)(C + (size_t)gr0 * Nt + gc) = o;
            }
            if (gr1 < M) {
                float2 o = make_float2(acc[i][j][2] + bi0, acc[i][j][3] + bi1);
                *(float2*)(C + (size_t)gr1 * Nt + gc) = o;
            }
        }
    }
}

// ================= fused per-node edge kernel =================
// One warp per dst node. h[dst] += softmax-weighted sum of v[src]. No atomics.
__global__ __launch_bounds__(256)
void edge_fused_kernel(int Nn, int d, int h_sel, float inv_sqrt_d) {
    __shared__ float sc[8][DEG_CAP];
    int gw = (blockIdx.x * blockDim.x + threadIdx.x) >> 5;
    int lane = threadIdx.x & 31;
    int wIn = threadIdx.x >> 5;
    if (gw >= Nn) return;
    int beg = g_off[gw];
    int deg = g_off[gw + 1] - beg;
    if (deg == 0) return;

    const int nv = d >> 7;   // 1 (d=128) or 2 (d=256)
    const float* qr = g_q + (size_t)gw * d;
    float4 q0 = *(const float4*)(qr + lane * 4);
    float4 q1 = make_float4(0.f, 0.f, 0.f, 0.f);
    if (nv > 1) q1 = *(const float4*)(qr + 128 + lane * 4);

    // ---- pass 1: scores + max ----
    float mx = -FLT_MAX;
    for (int j = 0; j < deg; j++) {
        int s = g_ssrc[beg + j];
        const float* kr = g_k + (size_t)s * d;
        float4 b0 = *(const float4*)(kr + lane * 4);
        float sum = q0.x * b0.x + q0.y * b0.y + q0.z * b0.z + q0.w * b0.w;
        if (nv > 1) {
            float4 b1 = *(const float4*)(kr + 128 + lane * 4);
            sum += q1.x * b1.x + q1.y * b1.y + q1.z * b1.z + q1.w * b1.w;
        }
#pragma unroll
        for (int o = 16; o; o >>= 1) sum += __shfl_xor_sync(0xFFFFFFFFu, sum, o);
        sum *= inv_sqrt_d;
        mx = fmaxf(mx, sum);
        if (lane == 0) {
            if (j < DEG_CAP) sc[wIn][j] = sum;
            else g_score[beg + j] = sum;
        }
    }
    __syncwarp();

    // ---- pass 2: exp + denom ----
    float den = 0.f;
    for (int j = lane; j < deg; j += 32) {
        float v = (j < DEG_CAP) ? sc[wIn][j] : g_score[beg + j];
        float e = expf(v - mx);
        if (j < DEG_CAP) sc[wIn][j] = e;
        else g_score[beg + j] = e;
        den += e;
    }
#pragma unroll
    for (int o = 16; o; o >>= 1) den += __shfl_xor_sync(0xFFFFFFFFu, den, o);
    float rden = 1.f / den;
    __syncwarp();

    // ---- pass 3: weighted aggregate ----
    float4 a0 = make_float4(0.f, 0.f, 0.f, 0.f);
    float4 a1 = make_float4(0.f, 0.f, 0.f, 0.f);
    for (int j = 0; j < deg; j++) {
        int s = g_ssrc[beg + j];
        float e = (j < DEG_CAP) ? sc[wIn][j] : g_score[beg + j];
        float alpha = e * rden;
        const float* vr = g_v + (size_t)s * d;
        float4 b0 = *(const float4*)(vr + lane * 4);
        a0.x += alpha * b0.x; a0.y += alpha * b0.y;
        a0.z += alpha * b0.z; a0.w += alpha * b0.w;
        if (nv > 1) {
            float4 b1 = *(const float4*)(vr + 128 + lane * 4);
            a1.x += alpha * b1.x; a1.y += alpha * b1.y;
            a1.z += alpha * b1.z; a1.w += alpha * b1.w;
        }
    }

    float* hr = sel(h_sel) + (size_t)gw * d;
    float4 h0 = *(float4*)(hr + lane * 4);
    h0.x += a0.x; h0.y += a0.y; h0.z += a0.z; h0.w += a0.w;
    *(float4*)(hr + lane * 4) = h0;
    if (nv > 1) {
        float4 h1 = *(float4*)(hr + 128 + lane * 4);
        h1.x += a1.x; h1.y += a1.y; h1.z += a1.z; h1.w += a1.w;
        *(float4*)(hr + 128 + lane * 4) = h1;
    }
}

// ---------------- pooling ----------------
__global__ void pool_init_kernel() {
    int c = threadIdx.x;
    if (c < 256) {
        g_psum[c] = 0.f;
        g_pmax[c] = ENC_NEG_INF;
    }
}

__global__ void pool_kernel(int M, int d) {
    int c = threadIdx.x;
    const float* h = g_h2;
    float sum = 0.f, mx = -FLT_MAX;
    for (int r = blockIdx.x; r < M; r += gridDim.x) {
        float v = h[(size_t)r * d + c];
        sum += v;
        mx = fmaxf(mx, v);
    }
    atomicAdd(&g_psum[c], sum);
    atomicMax(&g_pmax[c], fenc(mx));
}

__global__ void pool_final_kernel(float* __restrict__ out, int M, int d) {
    int c = threadIdx.x;
    if (c < d) {
        out[c] = g_psum[c] / (float)M;
        out[d + c] = fdec(g_pmax[c]);
    }
}

// ---------------- launch ----------------
extern "C" void kernel_launch(void* const* d_in, const int* in_sizes, int n_in,
                              void* d_out, int out_size) {
    const float* x   = (const float*)d_in[0];
    const void*  ei  = d_in[1];
    const float* Wq1 = (const float*)d_in[3];
    const float* bq1 = (const float*)d_in[4];
    const float* Wk1 = (const float*)d_in[5];
    const float* bk1 = (const float*)d_in[6];
    const float* Wv1 = (const float*)d_in[7];
    const float* bv1 = (const float*)d_in[8];
    const float* Ws1 = (const float*)d_in[9];
    const float* bs1 = (const float*)d_in[10];
    const float* Wq2 = (const float*)d_in[11];
    const float* bq2 = (const float*)d_in[12];
    const float* Wk2 = (const float*)d_in[13];
    const float* bk2 = (const float*)d_in[14];
    const float* Wv2 = (const float*)d_in[15];
    const float* bv2 = (const float*)d_in[16];
    const float* Ws2 = (const float*)d_in[17];
    const float* bs2 = (const float*)d_in[18];
    float* out = (float*)d_out;

    const int D_IN = 512, D_HID = 256, D_OUT = 128;
    int Nn = in_sizes[0] / D_IN;
    int E  = in_sizes[2];

    static int smem_set = 0;
    if (!smem_set) {
        cudaFuncSetAttribute(gemm_mma_kernel,
                             cudaFuncAttributeMaxDynamicSharedMemorySize, GEMM_SMEM);
        smem_set = 1;
    }

    // ---- graph preprocessing: CSR by dst ----
    detect_kernel<<<1, 32>>>((const unsigned*)ei, E);
    zero_deg_kernel<<<(Nn + 255) / 256, 256>>>(Nn);
    convert_kernel<<<(E + 255) / 256, 256>>>(ei, E);
    scan_kernel<<<1, 1024>>>(Nn);
    permute_kernel<<<(E + 255) / 256, 256>>>(E);

    int nTiles = (Nn + 127) / 128;
    int edgeBlks = (Nn * 32 + 255) / 256;

    // ===== layer 1 =====
    {
        dim3 g(8, nTiles);
        gemm_mma_kernel<<<g, 256, GEMM_SMEM>>>(
            x, -1, Wq1, Wk1, Wv1, Ws1, bq1, bk1, bv1, bs1,
            0, 1, 2, 3, Nn, D_IN, D_HID, 1);
    }
    edge_fused_kernel<<<edgeBlks, 256>>>(Nn, D_HID, 3,
        (float)(1.0 / sqrt((double)D_HID)));

    // ===== layer 2 =====
    {
        dim3 g(4, nTiles);
        gemm_mma_kernel<<<g, 256, GEMM_SMEM>>>(
            nullptr, 3, Wq2, Wk2, Wv2, Ws2, bq2, bk2, bv2, bs2,
            0, 1, 2, 4, Nn, D_HID, D_OUT, 0);
    }
    edge_fused_kernel<<<edgeBlks, 256>>>(Nn, D_OUT, 4,
        (float)(1.0 / sqrt((double)D_OUT)));

    // ===== pooling =====
    pool_init_kernel<<<1, 256>>>();
    pool_kernel<<<256, D_OUT>>>(Nn, D_OUT);
    pool_final_kernel<<<1, 256>>>(out, Nn, D_OUT);
}

// round 7
// speedup vs baseline: 2.7036x; 1.0882x over previous
#include <cuda_runtime.h>
#include <cuda_bf16.h>
#include <math.h>
#include <float.h>
#include <stdint.h>

#define MAXN 50000
#define MAXE 800000
#define DMAX 256
#define DEG_CAP 64

// ---------------- static device scratch ----------------
__device__ float g_q[(size_t)MAXN * DMAX];
__device__ float g_k[(size_t)MAXN * DMAX];
__device__ float g_v[(size_t)MAXN * DMAX];
__device__ float g_h1[(size_t)MAXN * DMAX];
__device__ float g_h2[(size_t)MAXN * DMAX];
__device__ float g_score[MAXE];      // spill for deg > DEG_CAP
__device__ int g_src[MAXE];
__device__ int g_dst[MAXE];
__device__ int g_ssrc[MAXE];         // src sorted by dst
__device__ int g_deg[MAXN];
__device__ int g_off[MAXN + 1];
__device__ int g_cursor[MAXN];
__device__ int g_part[256];
__device__ int g_is64;
__device__ float g_psum[256];
__device__ unsigned g_pmax[256];

__device__ __forceinline__ float* sel(int w) {
    switch (w) {
        case 0: return g_q;
        case 1: return g_k;
        case 2: return g_v;
        case 3: return g_h1;
        default: return g_h2;
    }
}

__device__ __forceinline__ unsigned fenc(float f) {
    unsigned u = __float_as_uint(f);
    return (u & 0x80000000u) ? ~u : (u | 0x80000000u);
}
__device__ __forceinline__ float fdec(unsigned u) {
    u = (u & 0x80000000u) ? (u ^ 0x80000000u) : ~u;
    return __uint_as_float(u);
}
#define ENC_NEG_INF 0x007FFFFFu

// ---------------- PTX helpers ----------------
__device__ __forceinline__ uint32_t smem_u32(const void* p) {
    uint32_t a;
    asm("{ .reg .u64 t; cvta.to.shared.u64 t, %1; cvt.u32.u64 %0, t; }" : "=r"(a) : "l"(p));
    return a;
}

__device__ __forceinline__ void ldm_x4(uint32_t& r0, uint32_t& r1, uint32_t& r2, uint32_t& r3,
                                       uint32_t addr) {
    asm volatile("ldmatrix.sync.aligned.m8n8.x4.shared.b16 {%0,%1,%2,%3}, [%4];"
        : "=r"(r0), "=r"(r1), "=r"(r2), "=r"(r3) : "r"(addr));
}

__device__ __forceinline__ void mma_bf16(float* c, const uint32_t* a, const uint32_t* b) {
    asm volatile("mma.sync.aligned.m16n8k16.row.col.f32.bf16.bf16.f32 "
        "{%0,%1,%2,%3}, {%4,%5,%6,%7}, {%8,%9}, {%0,%1,%2,%3};"
        : "+f"(c[0]), "+f"(c[1]), "+f"(c[2]), "+f"(c[3])
        : "r"(a[0]), "r"(a[1]), "r"(a[2]), "r"(a[3]), "r"(b[0]), "r"(b[1]));
}

__device__ __forceinline__ uint32_t pack_bf(float a, float b) {
    __nv_bfloat162 t = __floats2bfloat162_rn(a, b);
    return *(uint32_t*)&t;
}
__device__ __forceinline__ float bf_hi_val(float v, float& lo) {
    __nv_bfloat16 h = __float2bfloat16_rn(v);
    float hf = __bfloat162float(h);
    lo = v - hf;
    return hf;
}

// ---------------- graph preprocessing ----------------
__global__ void detect_kernel(const unsigned* __restrict__ ei, int E) {
    if (threadIdx.x == 0 && blockIdx.x == 0) {
        int n = E < 64 ? E : 64;
        int is64 = 1;
        for (int i = 0; i < n; i++) {
            if (ei[2 * i + 1] != 0u) { is64 = 0; break; }
        }
        g_is64 = is64;
    }
}

__global__ void zero_deg_kernel(int Nn) {
    int i = blockIdx.x * blockDim.x + threadIdx.x;
    if (i < Nn) g_deg[i] = 0;
}

// convert + histogram fused
__global__ void convert_kernel(const void* __restrict__ ei, int E) {
    int i = blockIdx.x * blockDim.x + threadIdx.x;
    if (i >= E) return;
    int s, t;
    if (g_is64) {
        const long long* p = (const long long*)ei;
        s = (int)p[i];
        t = (int)p[E + i];
    } else {
        const int* p = (const int*)ei;
        s = p[i];
        t = p[E + i];
    }
    g_src[i] = s;
    g_dst[i] = t;
    atomicAdd(&g_deg[t], 1);
}

// ---- 3-stage parallel exclusive scan over degrees ----
__global__ void part_sum_kernel(int Nn) {
    __shared__ int red[256];
    int t = threadIdx.x;
    int i = blockIdx.x * 256 + t;
    red[t] = (i < Nn) ? g_deg[i] : 0;
    __syncthreads();
    for (int o = 128; o; o >>= 1) {
        if (t < o) red[t] += red[t + o];
        __syncthreads();
    }
    if (t == 0) g_part[blockIdx.x] = red[0];
}

__global__ void part_scan_kernel(int nb, int Nn) {
    __shared__ int s[256];
    int t = threadIdx.x;
    s[t] = (t < nb) ? g_part[t] : 0;
    __syncthreads();
    for (int o = 1; o < 256; o <<= 1) {
        int u = (t >= o) ? s[t - o] : 0;
        __syncthreads();
        s[t] += u;
        __syncthreads();
    }
    g_part[t] = (t > 0) ? s[t - 1] : 0;
    if (t == 255) g_off[Nn] = s[255];
}

__global__ void off_kernel(int Nn) {
    __shared__ int s[256];
    int t = threadIdx.x;
    int i = blockIdx.x * 256 + t;
    int v = (i < Nn) ? g_deg[i] : 0;
    s[t] = v;
    __syncthreads();
    for (int o = 1; o < 256; o <<= 1) {
        int u = (t >= o) ? s[t - o] : 0;
        __syncthreads();
        s[t] += u;
        __syncthreads();
    }
    if (i < Nn) {
        int excl = s[t] - v + g_part[blockIdx.x];
        g_off[i] = excl;
        g_cursor[i] = excl;
    }
}

__global__ void permute_kernel(int E) {
    int i = blockIdx.x * blockDim.x + threadIdx.x;
    if (i >= E) return;
    int t = g_dst[i];
    int pos = atomicAdd(&g_cursor[t], 1);
    g_ssrc[pos] = g_src[i];
}

// ================= bf16 mma.sync GEMM (3xBF16 compensated) =================
#define OFF_AH 0
#define OFF_AL 10240
#define OFF_BH 20480
#define OFF_BL 30720
#define BUF_SZ 40960
#define GEMM_SMEM (2 * BUF_SZ)

__global__ __launch_bounds__(256, 1)
void gemm_mma_kernel(const float* __restrict__ Aext, int a_sel,
                     const float* __restrict__ W0, const float* __restrict__ W1,
                     const float* __restrict__ W2, const float* __restrict__ W3,
                     const float* __restrict__ b0, const float* __restrict__ b1,
                     const float* __restrict__ b2, const float* __restrict__ b3,
                     int c0, int c1, int c2, int c3,
                     int M, int K, int Nt, int sanitize) {
    extern __shared__ char smem[];
    const uint32_t sbase = smem_u32(smem);

    const int tid = threadIdx.x;
    const int wid = tid >> 5;
    const int lid = tid & 31;
    const int wm = wid & 1;
    const int wn = wid >> 1;
    const int rowBase = blockIdx.y * 128;

    const int cbPerW = Nt >> 7;
    const int wsel = blockIdx.x / cbPerW;
    const int colBase = (blockIdx.x - wsel * cbPerW) * 128;

    const float* A = (a_sel >= 0) ? sel(a_sel) : Aext;
    const float* W;
    const float* bias;
    int csel;
    switch (wsel) {
        case 0: W = W0; bias = b0; csel = c0; break;
        case 1: W = W1; bias = b1; csel = c1; break;
        case 2: W = W2; bias = b2; csel = c2; break;
        default: W = W3; bias = b3; csel = c3; break;
    }
    float* C = sel(csel);

    float acc[4][4][4];
#pragma unroll
    for (int i = 0; i < 4; i++)
#pragma unroll
        for (int j = 0; j < 4; j++)
#pragma unroll
            for (int q = 0; q < 4; q++) acc[i][j][q] = 0.f;

    const int a_row = tid >> 3;
    const int a_kq = tid & 7;
    const int w_n = tid & 127;
    const int w_kp0 = tid >> 7;

    float4 aV[4];
    float wv0[8], wv1[8];

    const int nChunks = K >> 5;

    {
        const int k0 = 0;
#pragma unroll
        for (int i = 0; i < 4; i++) {
            int row = a_row + i * 32;
            int gr = rowBase + row;
            float4 v = make_float4(0.f, 0.f, 0.f, 0.f);
            if (gr < M) v = *(const float4*)(A + (size_t)gr * K + k0 + a_kq * 4);
            if (sanitize) {
                if (v.x != v.x) v.x = 0.f;
                if (v.y != v.y) v.y = 0.f;
                if (v.z != v.z) v.z = 0.f;
                if (v.w != v.w) v.w = 0.f;
            }
            aV[i] = v;
        }
#pragma unroll
        for (int i = 0; i < 8; i++) {
            int kp = w_kp0 + i * 2;
            wv0[i] = W[(size_t)(k0 + kp * 2) * Nt + colBase + w_n];
            wv1[i] = W[(size_t)(k0 + kp * 2 + 1) * Nt + colBase + w_n];
        }
    }

    int buf = 0;
    for (int c = 0; c < nChunks; c++) {
        uint32_t bb = sbase + buf * BUF_SZ;
#pragma unroll
        for (int i = 0; i < 4; i++) {
            int row = a_row + i * 32;
            float lox, loy, loz, low;
            float hx = bf_hi_val(aV[i].x, lox);
            float hy = bf_hi_val(aV[i].y, loy);
            float hz = bf_hi_val(aV[i].z, loz);
            float hw = bf_hi_val(aV[i].w, low);
            uint2 hi = make_uint2(pack_bf(hx, hy), pack_bf(hz, hw));
            uint2 lo = make_uint2(pack_bf(lox, loy), pack_bf(loz, low));
            uint32_t off = (uint32_t)(row * 80 + a_kq * 8);
            *(uint2*)(smem + (buf * BUF_SZ + OFF_AH) + off) = hi;
            *(uint2*)(smem + (buf * BUF_SZ + OFF_AL) + off) = lo;
        }
#pragma unroll
        for (int i = 0; i < 8; i++) {
            int kp = w_kp0 + i * 2;
            float lo0, lo1;
            float h0 = bf_hi_val(wv0[i], lo0);
            float h1 = bf_hi_val(wv1[i], lo1);
            uint32_t off = (uint32_t)(w_n * 80 + kp * 4);
            *(uint32_t*)(smem + (buf * BUF_SZ + OFF_BH) + off) = pack_bf(h0, h1);
            *(uint32_t*)(smem + (buf * BUF_SZ + OFF_BL) + off) = pack_bf(lo0, lo1);
        }
        __syncthreads();

        if (c + 1 < nChunks) {
            const int k0 = (c + 1) << 5;
#pragma unroll
            for (int i = 0; i < 4; i++) {
                int row = a_row + i * 32;
                int gr = rowBase + row;
                float4 v = make_float4(0.f, 0.f, 0.f, 0.f);
                if (gr < M) v = *(const float4*)(A + (size_t)gr * K + k0 + a_kq * 4);
                if (sanitize) {
                    if (v.x != v.x) v.x = 0.f;
                    if (v.y != v.y) v.y = 0.f;
                    if (v.z != v.z) v.z = 0.f;
                    if (v.w != v.w) v.w = 0.f;
                }
                aV[i] = v;
            }
#pragma unroll
            for (int i = 0; i < 8; i++) {
                int kp = w_kp0 + i * 2;
                wv0[i] = W[(size_t)(k0 + kp * 2) * Nt + colBase + w_n];
                wv1[i] = W[(size_t)(k0 + kp * 2 + 1) * Nt + colBase + w_n];
            }
        }

        const int lr = lid & 15;
        const int lc = lid >> 4;
        uint32_t AHB = bb + OFF_AH, ALB = bb + OFF_AL;
        uint32_t BHB = bb + OFF_BH, BLB = bb + OFF_BL;
#pragma unroll
        for (int ks = 0; ks < 2; ks++) {
            uint32_t koff = (uint32_t)(ks * 32 + lc * 16);
            uint32_t ah[4][4], al[4][4], bh[4][2], bl[4][2];
#pragma unroll
            for (int i = 0; i < 4; i++) {
                uint32_t ro = (uint32_t)((wm * 64 + i * 16 + lr) * 80) + koff;
                ldm_x4(ah[i][0], ah[i][1], ah[i][2], ah[i][3], AHB + ro);
                ldm_x4(al[i][0], al[i][1], al[i][2], al[i][3], ALB + ro);
            }
#pragma unroll
            for (int j2 = 0; j2 < 2; j2++) {
                uint32_t ro = (uint32_t)((wn * 32 + j2 * 16 + lr) * 80) + koff;
                uint32_t r0, r1, r2, r3;
                ldm_x4(r0, r1, r2, r3, BHB + ro);
                bh[j2 * 2 + 0][0] = r0; bh[j2 * 2 + 0][1] = r2;
                bh[j2 * 2 + 1][0] = r1; bh[j2 * 2 + 1][1] = r3;
                ldm_x4(r0, r1, r2, r3, BLB + ro);
                bl[j2 * 2 + 0][0] = r0; bl[j2 * 2 + 0][1] = r2;
                bl[j2 * 2 + 1][0] = r1; bl[j2 * 2 + 1][1] = r3;
            }
#pragma unroll
            for (int i = 0; i < 4; i++)
#pragma unroll
                for (int j = 0; j < 4; j++) {
                    mma_bf16(acc[i][j], ah[i], bh[j]);
                    mma_bf16(acc[i][j], ah[i], bl[j]);
                    mma_bf16(acc[i][j], al[i], bh[j]);
                }
        }
        __syncthreads();
        buf ^= 1;
    }

    const int lr4 = lid >> 2;
    const int lc2 = (lid & 3) * 2;
#pragma unroll
    for (int j = 0; j < 4; j++) {
        int gc = colBase + wn * 32 + j * 8 + lc2;
        float bi0 = bias[gc], bi1 = bias[gc + 1];
#pragma unroll
        for (int i = 0; i < 4; i++) {
            int gr0 = rowBase + wm * 64 + i * 16 + lr4;
            int gr1 = gr0 + 8;
            if (gr0 < M) {
                float2 o = make_float2(acc[i][j][0] + bi0, acc[i][j][1] + bi1);
                *(float2*)(C + (size_t)gr0 * Nt + gc) = o;
            }
            if (gr1 < M) {
                float2 o = make_float2(acc[i][j][2] + bi0, acc[i][j][3] + bi1);
                *(float2*)(C + (size_t)gr1 * Nt + gc) = o;
            }
        }
    }
}

// ================= fused per-node edge kernel (2-edge pipelined) =================
__global__ __launch_bounds__(256)
void edge_fused_kernel(int Nn, int d, int h_sel, float inv_sqrt_d) {
    __shared__ float sc[8][DEG_CAP];
    int gw = (blockIdx.x * blockDim.x + threadIdx.x) >> 5;
    int lane = threadIdx.x & 31;
    int wIn = threadIdx.x >> 5;
    if (gw >= Nn) return;
    int beg = g_off[gw];
    int deg = g_off[gw + 1] - beg;
    if (deg == 0) return;

    const int nv = d >> 7;   // 1 (d=128) or 2 (d=256)
    const float* qr = g_q + (size_t)gw * d;
    float4 q0 = *(const float4*)(qr + lane * 4);
    float4 q1 = make_float4(0.f, 0.f, 0.f, 0.f);
    if (nv > 1) q1 = *(const float4*)(qr + 128 + lane * 4);

    // ---- pass 1: scores + max (2 edges per iteration) ----
    float mx = -FLT_MAX;
    int j = 0;
    for (; j + 1 < deg; j += 2) {
        int s0 = g_ssrc[beg + j];
        int s1 = g_ssrc[beg + j + 1];
        const float* k0p = g_k + (size_t)s0 * d;
        const float* k1p = g_k + (size_t)s1 * d;
        float4 b0 = *(const float4*)(k0p + lane * 4);
        float4 c0 = *(const float4*)(k1p + lane * 4);
        float sa = q0.x * b0.x + q0.y * b0.y + q0.z * b0.z + q0.w * b0.w;
        float sb = q0.x * c0.x + q0.y * c0.y + q0.z * c0.z + q0.w * c0.w;
        if (nv > 1) {
            float4 b1 = *(const float4*)(k0p + 128 + lane * 4);
            float4 c1 = *(const float4*)(k1p + 128 + lane * 4);
            sa += q1.x * b1.x + q1.y * b1.y + q1.z * b1.z + q1.w * b1.w;
            sb += q1.x * c1.x + q1.y * c1.y + q1.z * c1.z + q1.w * c1.w;
        }
#pragma unroll
        for (int o = 16; o; o >>= 1) {
            sa += __shfl_xor_sync(0xFFFFFFFFu, sa, o);
            sb += __shfl_xor_sync(0xFFFFFFFFu, sb, o);
        }
        sa *= inv_sqrt_d;
        sb *= inv_sqrt_d;
        mx = fmaxf(mx, fmaxf(sa, sb));
        if (lane == 0) {
            if (j < DEG_CAP) sc[wIn][j] = sa; else g_score[beg + j] = sa;
            if (j + 1 < DEG_CAP) sc[wIn][j + 1] = sb; else g_score[beg + j + 1] = sb;
        }
    }
    if (j < deg) {
        int s = g_ssrc[beg + j];
        const float* kr = g_k + (size_t)s * d;
        float4 b0 = *(const float4*)(kr + lane * 4);
        float sum = q0.x * b0.x + q0.y * b0.y + q0.z * b0.z + q0.w * b0.w;
        if (nv > 1) {
            float4 b1 = *(const float4*)(kr + 128 + lane * 4);
            sum += q1.x * b1.x + q1.y * b1.y + q1.z * b1.z + q1.w * b1.w;
        }
#pragma unroll
        for (int o = 16; o; o >>= 1) sum += __shfl_xor_sync(0xFFFFFFFFu, sum, o);
        sum *= inv_sqrt_d;
        mx = fmaxf(mx, sum);
        if (lane == 0) {
            if (j < DEG_CAP) sc[wIn][j] = sum; else g_score[beg + j] = sum;
        }
    }
    __syncwarp();

    // ---- pass 2: exp + denom ----
    float den = 0.f;
    for (int jj = lane; jj < deg; jj += 32) {
        float v = (jj < DEG_CAP) ? sc[wIn][jj] : g_score[beg + jj];
        float e = expf(v - mx);
        if (jj < DEG_CAP) sc[wIn][jj] = e;
        else g_score[beg + jj] = e;
        den += e;
    }
#pragma unroll
    for (int o = 16; o; o >>= 1) den += __shfl_xor_sync(0xFFFFFFFFu, den, o);
    float rden = 1.f / den;
    __syncwarp();

    // ---- pass 3: weighted aggregate (2 edges per iteration) ----
    float4 a0 = make_float4(0.f, 0.f, 0.f, 0.f);
    float4 a1 = make_float4(0.f, 0.f, 0.f, 0.f);
    j = 0;
    for (; j + 1 < deg; j += 2) {
        int s0 = g_ssrc[beg + j];
        int s1 = g_ssrc[beg + j + 1];
        float e0 = (j < DEG_CAP) ? sc[wIn][j] : g_score[beg + j];
        float e1 = (j + 1 < DEG_CAP) ? sc[wIn][j + 1] : g_score[beg + j + 1];
        float al0 = e0 * rden, al1 = e1 * rden;
        const float* v0p = g_v + (size_t)s0 * d;
        const float* v1p = g_v + (size_t)s1 * d;
        float4 b0 = *(const float4*)(v0p + lane * 4);
        float4 c0 = *(const float4*)(v1p + lane * 4);
        a0.x += al0 * b0.x + al1 * c0.x;
        a0.y += al0 * b0.y + al1 * c0.y;
        a0.z += al0 * b0.z + al1 * c0.z;
        a0.w += al0 * b0.w + al1 * c0.w;
        if (nv > 1) {
            float4 b1 = *(const float4*)(v0p + 128 + lane * 4);
            float4 c1 = *(const float4*)(v1p + 128 + lane * 4);
            a1.x += al0 * b1.x + al1 * c1.x;
            a1.y += al0 * b1.y + al1 * c1.y;
            a1.z += al0 * b1.z + al1 * c1.z;
            a1.w += al0 * b1.w + al1 * c1.w;
        }
    }
    if (j < deg) {
        int s = g_ssrc[beg + j];
        float e = (j < DEG_CAP) ? sc[wIn][j] : g_score[beg + j];
        float alpha = e * rden;
        const float* vr = g_v + (size_t)s * d;
        float4 b0 = *(const float4*)(vr + lane * 4);
        a0.x += alpha * b0.x; a0.y += alpha * b0.y;
        a0.z += alpha * b0.z; a0.w += alpha * b0.w;
        if (nv > 1) {
            float4 b1 = *(const float4*)(vr + 128 + lane * 4);
            a1.x += alpha * b1.x; a1.y += alpha * b1.y;
            a1.z += alpha * b1.z; a1.w += alpha * b1.w;
        }
    }

    float* hr = sel(h_sel) + (size_t)gw * d;
    float4 h0 = *(float4*)(hr + lane * 4);
    h0.x += a0.x; h0.y += a0.y; h0.z += a0.z; h0.w += a0.w;
    *(float4*)(hr + lane * 4) = h0;
    if (nv > 1) {
        float4 h1 = *(float4*)(hr + 128 + lane * 4);
        h1.x += a1.x; h1.y += a1.y; h1.z += a1.z; h1.w += a1.w;
        *(float4*)(hr + 128 + lane * 4) = h1;
    }
}

// ---------------- pooling ----------------
__global__ void pool_init_kernel() {
    int c = threadIdx.x;
    if (c < 256) {
        g_psum[c] = 0.f;
        g_pmax[c] = ENC_NEG_INF;
    }
}

__global__ void pool_kernel(int M, int d) {
    int c = threadIdx.x;
    const float* h = g_h2;
    float sum = 0.f, mx = -FLT_MAX;
    for (int r = blockIdx.x; r < M; r += gridDim.x) {
        float v = h[(size_t)r * d + c];
        sum += v;
        mx = fmaxf(mx, v);
    }
    atomicAdd(&g_psum[c], sum);
    atomicMax(&g_pmax[c], fenc(mx));
}

__global__ void pool_final_kernel(float* __restrict__ out, int M, int d) {
    int c = threadIdx.x;
    if (c < d) {
        out[c] = g_psum[c] / (float)M;
        out[d + c] = fdec(g_pmax[c]);
    }
}

// ---------------- launch ----------------
extern "C" void kernel_launch(void* const* d_in, const int* in_sizes, int n_in,
                              void* d_out, int out_size) {
    const float* x   = (const float*)d_in[0];
    const void*  ei  = d_in[1];
    const float* Wq1 = (const float*)d_in[3];
    const float* bq1 = (const float*)d_in[4];
    const float* Wk1 = (const float*)d_in[5];
    const float* bk1 = (const float*)d_in[6];
    const float* Wv1 = (const float*)d_in[7];
    const float* bv1 = (const float*)d_in[8];
    const float* Ws1 = (const float*)d_in[9];
    const float* bs1 = (const float*)d_in[10];
    const float* Wq2 = (const float*)d_in[11];
    const float* bq2 = (const float*)d_in[12];
    const float* Wk2 = (const float*)d_in[13];
    const float* bk2 = (const float*)d_in[14];
    const float* Wv2 = (const float*)d_in[15];
    const float* bv2 = (const float*)d_in[16];
    const float* Ws2 = (const float*)d_in[17];
    const float* bs2 = (const float*)d_in[18];
    float* out = (float*)d_out;

    const int D_IN = 512, D_HID = 256, D_OUT = 128;
    int Nn = in_sizes[0] / D_IN;
    int E  = in_sizes[2];

    static int smem_set = 0;
    if (!smem_set) {
        cudaFuncSetAttribute(gemm_mma_kernel,
                             cudaFuncAttributeMaxDynamicSharedMemorySize, GEMM_SMEM);
        smem_set = 1;
    }

    // ---- graph preprocessing: CSR by dst ----
    int nb = (Nn + 255) / 256;
    detect_kernel<<<1, 32>>>((const unsigned*)ei, E);
    zero_deg_kernel<<<nb, 256>>>(Nn);
    convert_kernel<<<(E + 255) / 256, 256>>>(ei, E);
    part_sum_kernel<<<nb, 256>>>(Nn);
    part_scan_kernel<<<1, 256>>>(nb, Nn);
    off_kernel<<<nb, 256>>>(Nn);
    permute_kernel<<<(E + 255) / 256, 256>>>(E);

    int nTiles = (Nn + 127) / 128;
    int edgeBlks = (Nn * 32 + 255) / 256;

    // ===== layer 1 =====
    {
        dim3 g(8, nTiles);
        gemm_mma_kernel<<<g, 256, GEMM_SMEM>>>(
            x, -1, Wq1, Wk1, Wv1, Ws1, bq1, bk1, bv1, bs1,
            0, 1, 2, 3, Nn, D_IN, D_HID, 1);
    }
    edge_fused_kernel<<<edgeBlks, 256>>>(Nn, D_HID, 3,
        (float)(1.0 / sqrt((double)D_HID)));

    // ===== layer 2 =====
    {
        dim3 g(4, nTiles);
        gemm_mma_kernel<<<g, 256, GEMM_SMEM>>>(
            nullptr, 3, Wq2, Wk2, Wv2, Ws2, bq2, bk2, bv2, bs2,
            0, 1, 2, 4, Nn, D_HID, D_OUT, 0);
    }
    edge_fused_kernel<<<edgeBlks, 256>>>(Nn, D_OUT, 4,
        (float)(1.0 / sqrt((double)D_OUT)));

    // ===== pooling =====
    pool_init_kernel<<<1, 256>>>();
    pool_kernel<<<256, D_OUT>>>(Nn, D_OUT);
    pool_final_kernel<<<1, 256>>>(out, Nn, D_OUT);
}

// round 9
// speedup vs baseline: 3.2343x; 1.1963x over previous
#include <cuda_runtime.h>
#include <cuda_bf16.h>
#include <math.h>
#include <float.h>
#include <stdint.h>

#define MAXN 50000
#define MAXE 800000
#define DMAX 256
#define DEG_CAP 64

// ---------------- static device scratch ----------------
__device__ float g_q[(size_t)MAXN * DMAX];
__device__ float g_k[(size_t)MAXN * DMAX];
__device__ float g_v[(size_t)MAXN * DMAX];
__device__ float g_h1[(size_t)MAXN * DMAX];
__device__ float g_h2[(size_t)MAXN * DMAX];
__device__ float g_score[MAXE];
__device__ int g_src[MAXE];
__device__ int g_dst[MAXE];
__device__ int g_ssrc[MAXE];
__device__ int g_deg[MAXN];
__device__ int g_off[MAXN + 1];
__device__ int g_cursor[MAXN];
__device__ int g_part[256];
__device__ int g_is64;
__device__ float g_psum[256];
__device__ unsigned g_pmax[256];

// pre-split bf16 operands (16B-aligned via uint4 backing)
__device__ uint4 g_ah4[(size_t)MAXN * 512 / 8];   // A hi
__device__ uint4 g_al4[(size_t)MAXN * 512 / 8];   // A lo
__device__ uint4 g_wh4[81920];                     // W hi: L1 4x(512*256), L2 4x(256*128)
__device__ uint4 g_wl4[81920];                     // W lo
#define WOFF_L2 524288                             // element offset of layer-2 weights

__device__ __forceinline__ float* sel(int w) {
    switch (w) {
        case 0: return g_q;
        case 1: return g_k;
        case 2: return g_v;
        case 3: return g_h1;
        default: return g_h2;
    }
}

__device__ __forceinline__ unsigned fenc(float f) {
    unsigned u = __float_as_uint(f);
    return (u & 0x80000000u) ? ~u : (u | 0x80000000u);
}
__device__ __forceinline__ float fdec(unsigned u) {
    u = (u & 0x80000000u) ? (u ^ 0x80000000u) : ~u;
    return __uint_as_float(u);
}
#define ENC_NEG_INF 0x007FFFFFu

// ---------------- PTX helpers ----------------
__device__ __forceinline__ uint32_t smem_u32(const void* p) {
    uint32_t a;
    asm("{ .reg .u64 t; cvta.to.shared.u64 t, %1; cvt.u32.u64 %0, t; }" : "=r"(a) : "l"(p));
    return a;
}

__device__ __forceinline__ void ldm_x4(uint32_t& r0, uint32_t& r1, uint32_t& r2, uint32_t& r3,
                                       uint32_t addr) {
    asm volatile("ldmatrix.sync.aligned.m8n8.x4.shared.b16 {%0,%1,%2,%3}, [%4];"
        : "=r"(r0), "=r"(r1), "=r"(r2), "=r"(r3) : "r"(addr));
}

__device__ __forceinline__ void mma_bf16(float* c, const uint32_t* a, const uint32_t* b) {
    asm volatile("mma.sync.aligned.m16n8k16.row.col.f32.bf16.bf16.f32 "
        "{%0,%1,%2,%3}, {%4,%5,%6,%7}, {%8,%9}, {%0,%1,%2,%3};"
        : "+f"(c[0]), "+f"(c[1]), "+f"(c[2]), "+f"(c[3])
        : "r"(a[0]), "r"(a[1]), "r"(a[2]), "r"(a[3]), "r"(b[0]), "r"(b[1]));
}

__device__ __forceinline__ uint32_t pack_bf(float a, float b) {
    __nv_bfloat162 t = __floats2bfloat162_rn(a, b);
    return *(uint32_t*)&t;
}
__device__ __forceinline__ float bf_hi_val(float v, float& lo) {
    __nv_bfloat16 h = __float2bfloat16_rn(v);
    float hf = __bfloat162float(h);
    lo = v - hf;
    return hf;
}

// ---------------- graph preprocessing ----------------
__global__ void detect_kernel(const unsigned* __restrict__ ei, int E) {
    if (threadIdx.x == 0 && blockIdx.x == 0) {
        int n = E < 64 ? E : 64;
        int is64 = 1;
        for (int i = 0; i < n; i++) {
            if (ei[2 * i + 1] != 0u) { is64 = 0; break; }
        }
        g_is64 = is64;
    }
}

__global__ void zero_deg_kernel(int Nn) {
    int i = blockIdx.x * blockDim.x + threadIdx.x;
    if (i < Nn) g_deg[i] = 0;
}

__global__ void convert_kernel(const void* __restrict__ ei, int E) {
    int i = blockIdx.x * blockDim.x + threadIdx.x;
    if (i >= E) return;
    int s, t;
    if (g_is64) {
        const long long* p = (const long long*)ei;
        s = (int)p[i];
        t = (int)p[E + i];
    } else {
        const int* p = (const int*)ei;
        s = p[i];
        t = p[E + i];
    }
    g_src[i] = s;
    g_dst[i] = t;
    atomicAdd(&g_deg[t], 1);
}

__global__ void part_sum_kernel(int Nn) {
    __shared__ int red[256];
    int t = threadIdx.x;
    int i = blockIdx.x * 256 + t;
    red[t] = (i < Nn) ? g_deg[i] : 0;
    __syncthreads();
    for (int o = 128; o; o >>= 1) {
        if (t < o) red[t] += red[t + o];
        __syncthreads();
    }
    if (t == 0) g_part[blockIdx.x] = red[0];
}

__global__ void part_scan_kernel(int nb, int Nn) {
    __shared__ int s[256];
    int t = threadIdx.x;
    s[t] = (t < nb) ? g_part[t] : 0;
    __syncthreads();
    for (int o = 1; o < 256; o <<= 1) {
        int u = (t >= o) ? s[t - o] : 0;
        __syncthreads();
        s[t] += u;
        __syncthreads();
    }
    g_part[t] = (t > 0) ? s[t - 1] : 0;
    if (t == 255) g_off[Nn] = s[255];
}

__global__ void off_kernel(int Nn) {
    __shared__ int s[256];
    int t = threadIdx.x;
    int i = blockIdx.x * 256 + t;
    int v = (i < Nn) ? g_deg[i] : 0;
    s[t] = v;
    __syncthreads();
    for (int o = 1; o < 256; o <<= 1) {
        int u = (t >= o) ? s[t - o] : 0;
        __syncthreads();
        s[t] += u;
        __syncthreads();
    }
    if (i < Nn) {
        int excl = s[t] - v + g_part[blockIdx.x];
        g_off[i] = excl;
        g_cursor[i] = excl;
    }
}

__global__ void permute_kernel(int E) {
    int i = blockIdx.x * blockDim.x + threadIdx.x;
    if (i >= E) return;
    int t = g_dst[i];
    int pos = atomicAdd(&g_cursor[t], 1);
    g_ssrc[pos] = g_src[i];
}

// ---------------- operand pre-splitting ----------------
// A: fp32 [M,K] -> bf16 hi/lo, same layout (4 elems per thread)
__global__ void split_a_kernel(const float* __restrict__ Aext, int a_sel,
                               int total4, int sanitize) {
    int i = blockIdx.x * blockDim.x + threadIdx.x;
    if (i >= total4) return;
    const float* A = (a_sel >= 0) ? sel(a_sel) : Aext;
    float4 v = ((const float4*)A)[i];
    if (sanitize) {
        if (v.x != v.x) v.x = 0.f;
        if (v.y != v.y) v.y = 0.f;
        if (v.z != v.z) v.z = 0.f;
        if (v.w != v.w) v.w = 0.f;
    }
    float lx, ly, lz, lw;
    float hx = bf_hi_val(v.x, lx);
    float hy = bf_hi_val(v.y, ly);
    float hz = bf_hi_val(v.z, lz);
    float hw = bf_hi_val(v.w, lw);
    ((uint2*)g_ah4)[i] = make_uint2(pack_bf(hx, hy), pack_bf(hz, hw));
    ((uint2*)g_al4)[i] = make_uint2(pack_bf(lx, ly), pack_bf(lz, lw));
}

// W: fp32 [K,Nt] -> bf16 hi/lo transposed to [Nt,K], at element offset base + w*K*Nt
__global__ void split_w_kernel(const float* __restrict__ W0, const float* __restrict__ W1,
                               const float* __restrict__ W2, const float* __restrict__ W3,
                               int K, int Nt, int base) {
    int i = blockIdx.x * blockDim.x + threadIdx.x;
    if (i >= K * Nt) return;
    int w = blockIdx.y;
    const float* W = (w == 0) ? W0 : (w == 1) ? W1 : (w == 2) ? W2 : W3;
    int k = i / Nt, n = i - k * Nt;
    float v = W[i];
    float lo;
    float hi = bf_hi_val(v, lo);
    size_t o = (size_t)base + (size_t)w * K * Nt + (size_t)n * K + k;
    ((__nv_bfloat16*)g_wh4)[o] = __float2bfloat16_rn(hi);
    ((__nv_bfloat16*)g_wl4)[o] = __float2bfloat16_rn(lo);
}

// ================= bf16 mma.sync GEMM on pre-split operands =================
#define OFF_AH 0
#define OFF_AL 10240
#define OFF_BH 20480
#define OFF_BL 30720
#define BUF_SZ 40960
#define GEMM_SMEM (2 * BUF_SZ)

__global__ __launch_bounds__(256, 1)
void gemm_mma_kernel(int wbase,
                     const float* __restrict__ b0, const float* __restrict__ b1,
                     const float* __restrict__ b2, const float* __restrict__ b3,
                     int c0, int c1, int c2, int c3,
                     int M, int K, int Nt) {
    extern __shared__ char smem[];
    const uint32_t sbase = smem_u32(smem);

    const int tid = threadIdx.x;
    const int wid = tid >> 5;
    const int lid = tid & 31;
    const int wm = wid & 1;
    const int wn = wid >> 1;
    const int rowBase = blockIdx.y * 128;

    const int cbPerW = Nt >> 7;
    const int wsel = blockIdx.x / cbPerW;
    const int colBase = (blockIdx.x - wsel * cbPerW) * 128;

    const __nv_bfloat16* Ah = (const __nv_bfloat16*)g_ah4;
    const __nv_bfloat16* Al = (const __nv_bfloat16*)g_al4;
    const __nv_bfloat16* Wh = (const __nv_bfloat16*)g_wh4 + (size_t)wbase + (size_t)wsel * K * Nt;
    const __nv_bfloat16* Wl = (const __nv_bfloat16*)g_wl4 + (size_t)wbase + (size_t)wsel * K * Nt;

    const float* bias;
    int csel;
    switch (wsel) {
        case 0: bias = b0; csel = c0; break;
        case 1: bias = b1; csel = c1; break;
        case 2: bias = b2; csel = c2; break;
        default: bias = b3; csel = c3; break;
    }
    float* C = sel(csel);

    float acc[4][4][4];
#pragma unroll
    for (int i = 0; i < 4; i++)
#pragma unroll
        for (int j = 0; j < 4; j++)
#pragma unroll
            for (int q = 0; q < 4; q++) acc[i][j][q] = 0.f;

    // load mapping: idx = tid + i*256 in [0,512): row = idx>>2 (0..127), kq = idx&3 (8 bf16 each)
    const int l_row = tid >> 2;
    const int l_kq = tid & 3;

    uint4 aVh[2], aVl[2], wVh[2], wVl[2];
    const uint4 zz = make_uint4(0, 0, 0, 0);

    const int nChunks = K >> 5;

    // prefetch chunk 0
    {
        const int k0 = 0;
#pragma unroll
        for (int i = 0; i < 2; i++) {
            int row = l_row + i * 64;
            int gr = rowBase + row;
            if (gr < M) {
                aVh[i] = *(const uint4*)(Ah + (size_t)gr * K + k0 + l_kq * 8);
                aVl[i] = *(const uint4*)(Al + (size_t)gr * K + k0 + l_kq * 8);
            } else { aVh[i] = zz; aVl[i] = zz; }
            int n = colBase + row;
            wVh[i] = *(const uint4*)(Wh + (size_t)n * K + k0 + l_kq * 8);
            wVl[i] = *(const uint4*)(Wl + (size_t)n * K + k0 + l_kq * 8);
        }
    }

    int buf = 0;
    for (int c = 0; c < nChunks; c++) {
        // store prefetched chunk
        uint32_t bb = sbase + buf * BUF_SZ;
        {
            uint32_t off = (uint32_t)(l_row * 80 + l_kq * 16);
            *(uint4*)(smem + (buf * BUF_SZ + OFF_AH) + off) = aVh[0];
            *(uint4*)(smem + (buf * BUF_SZ + OFF_AL) + off) = aVl[0];
            *(uint4*)(smem + (buf * BUF_SZ + OFF_BH) + off) = wVh[0];
            *(uint4*)(smem + (buf * BUF_SZ + OFF_BL) + off) = wVl[0];
            uint32_t off2 = off + 64 * 80;
            *(uint4*)(smem + (buf * BUF_SZ + OFF_AH) + off2) = aVh[1];
            *(uint4*)(smem + (buf * BUF_SZ + OFF_AL) + off2) = aVl[1];
            *(uint4*)(smem + (buf * BUF_SZ + OFF_BH) + off2) = wVh[1];
            *(uint4*)(smem + (buf * BUF_SZ + OFF_BL) + off2) = wVl[1];
        }
        __syncthreads();

        // prefetch next chunk
        if (c + 1 < nChunks) {
            const int k0 = (c + 1) << 5;
#pragma unroll
            for (int i = 0; i < 2; i++) {
                int row = l_row + i * 64;
                int gr = rowBase + row;
                if (gr < M) {
                    aVh[i] = *(const uint4*)(Ah + (size_t)gr * K + k0 + l_kq * 8);
                    aVl[i] = *(const uint4*)(Al + (size_t)gr * K + k0 + l_kq * 8);
                } else { aVh[i] = zz; aVl[i] = zz; }
                int n = colBase + row;
                wVh[i] = *(const uint4*)(Wh + (size_t)n * K + k0 + l_kq * 8);
                wVl[i] = *(const uint4*)(Wl + (size_t)n * K + k0 + l_kq * 8);
            }
        }

        const int lr = lid & 15;
        const int lc = lid >> 4;
        uint32_t AHB = bb + OFF_AH, ALB = bb + OFF_AL;
        uint32_t BHB = bb + OFF_BH, BLB = bb + OFF_BL;
#pragma unroll
        for (int ks = 0; ks < 2; ks++) {
            uint32_t koff = (uint32_t)(ks * 32 + lc * 16);
            uint32_t ah[4][4], al[4][4], bh[4][2], bl[4][2];
#pragma unroll
            for (int i = 0; i < 4; i++) {
                uint32_t ro = (uint32_t)((wm * 64 + i * 16 + lr) * 80) + koff;
                ldm_x4(ah[i][0], ah[i][1], ah[i][2], ah[i][3], AHB + ro);
                ldm_x4(al[i][0], al[i][1], al[i][2], al[i][3], ALB + ro);
            }
#pragma unroll
            for (int j2 = 0; j2 < 2; j2++) {
                uint32_t ro = (uint32_t)((wn * 32 + j2 * 16 + lr) * 80) + koff;
                uint32_t r0, r1, r2, r3;
                ldm_x4(r0, r1, r2, r3, BHB + ro);
                bh[j2 * 2 + 0][0] = r0; bh[j2 * 2 + 0][1] = r2;
                bh[j2 * 2 + 1][0] = r1; bh[j2 * 2 + 1][1] = r3;
                ldm_x4(r0, r1, r2, r3, BLB + ro);
                bl[j2 * 2 + 0][0] = r0; bl[j2 * 2 + 0][1] = r2;
                bl[j2 * 2 + 1][0] = r1; bl[j2 * 2 + 1][1] = r3;
            }
#pragma unroll
            for (int i = 0; i < 4; i++)
#pragma unroll
                for (int j = 0; j < 4; j++) {
                    mma_bf16(acc[i][j], ah[i], bh[j]);
                    mma_bf16(acc[i][j], ah[i], bl[j]);
                    mma_bf16(acc[i][j], al[i], bh[j]);
                }
        }
        __syncthreads();
        buf ^= 1;
    }

    const int lr4 = lid >> 2;
    const int lc2 = (lid & 3) * 2;
#pragma unroll
    for (int j = 0; j < 4; j++) {
        int gc = colBase + wn * 32 + j * 8 + lc2;
        float bi0 = bias[gc], bi1 = bias[gc + 1];
#pragma unroll
        for (int i = 0; i < 4; i++) {
            int gr0 = rowBase + wm * 64 + i * 16 + lr4;
            int gr1 = gr0 + 8;
            if (gr0 < M) {
                float2 o = make_float2(acc[i][j][0] + bi0, acc[i][j][1] + bi1);
                *(float2*)(C + (size_t)gr0 * Nt + gc) = o;
            }
            if (gr1 < M) {
                float2 o = make_float2(acc[i][j][2] + bi0, acc[i][j][3] + bi1);
                *(float2*)(C + (size_t)gr1 * Nt + gc) = o;
            }
        }
    }
}

// ================= fused per-node edge kernel (2-edge pipelined) =================
__global__ __launch_bounds__(256)
void edge_fused_kernel(int Nn, int d, int h_sel, float inv_sqrt_d) {
    __shared__ float sc[8][DEG_CAP];
    int gw = (blockIdx.x * blockDim.x + threadIdx.x) >> 5;
    int lane = threadIdx.x & 31;
    int wIn = threadIdx.x >> 5;
    if (gw >= Nn) return;
    int beg = g_off[gw];
    int deg = g_off[gw + 1] - beg;
    if (deg == 0) return;

    const int nv = d >> 7;
    const float* qr = g_q + (size_t)gw * d;
    float4 q0 = *(const float4*)(qr + lane * 4);
    float4 q1 = make_float4(0.f, 0.f, 0.f, 0.f);
    if (nv > 1) q1 = *(const float4*)(qr + 128 + lane * 4);

    float mx = -FLT_MAX;
    int j = 0;
    for (; j + 1 < deg; j += 2) {
        int s0 = g_ssrc[beg + j];
        int s1 = g_ssrc[beg + j + 1];
        const float* k0p = g_k + (size_t)s0 * d;
        const float* k1p = g_k + (size_t)s1 * d;
        float4 b0 = *(const float4*)(k0p + lane * 4);
        float4 c0 = *(const float4*)(k1p + lane * 4);
        float sa = q0.x * b0.x + q0.y * b0.y + q0.z * b0.z + q0.w * b0.w;
        float sb = q0.x * c0.x + q0.y * c0.y + q0.z * c0.z + q0.w * c0.w;
        if (nv > 1) {
            float4 b1 = *(const float4*)(k0p + 128 + lane * 4);
            float4 c1 = *(const float4*)(k1p + 128 + lane * 4);
            sa += q1.x * b1.x + q1.y * b1.y + q1.z * b1.z + q1.w * b1.w;
            sb += q1.x * c1.x + q1.y * c1.y + q1.z * c1.z + q1.w * c1.w;
        }
#pragma unroll
        for (int o = 16; o; o >>= 1) {
            sa += __shfl_xor_sync(0xFFFFFFFFu, sa, o);
            sb += __shfl_xor_sync(0xFFFFFFFFu, sb, o);
        }
        sa *= inv_sqrt_d;
        sb *= inv_sqrt_d;
        mx = fmaxf(mx, fmaxf(sa, sb));
        if (lane == 0) {
            if (j < DEG_CAP) sc[wIn][j] = sa; else g_score[beg + j] = sa;
            if (j + 1 < DEG_CAP) sc[wIn][j + 1] = sb; else g_score[beg + j + 1] = sb;
        }
    }
    if (j < deg) {
        int s = g_ssrc[beg + j];
        const float* kr = g_k + (size_t)s * d;
        float4 b0 = *(const float4*)(kr + lane * 4);
        float sum = q0.x * b0.x + q0.y * b0.y + q0.z * b0.z + q0.w * b0.w;
        if (nv > 1) {
            float4 b1 = *(const float4*)(kr + 128 + lane * 4);
            sum += q1.x * b1.x + q1.y * b1.y + q1.z * b1.z + q1.w * b1.w;
        }
#pragma unroll
        for (int o = 16; o; o >>= 1) sum += __shfl_xor_sync(0xFFFFFFFFu, sum, o);
        sum *= inv_sqrt_d;
        mx = fmaxf(mx, sum);
        if (lane == 0) {
            if (j < DEG_CAP) sc[wIn][j] = sum; else g_score[beg + j] = sum;
        }
    }
    __syncwarp();

    float den = 0.f;
    for (int jj = lane; jj < deg; jj += 32) {
        float v = (jj < DEG_CAP) ? sc[wIn][jj] : g_score[beg + jj];
        float e = expf(v - mx);
        if (jj < DEG_CAP) sc[wIn][jj] = e;
        else g_score[beg + jj] = e;
        den += e;
    }
#pragma unroll
    for (int o = 16; o; o >>= 1) den += __shfl_xor_sync(0xFFFFFFFFu, den, o);
    float rden = 1.f / den;
    __syncwarp();

    float4 a0 = make_float4(0.f, 0.f, 0.f, 0.f);
    float4 a1 = make_float4(0.f, 0.f, 0.f, 0.f);
    j = 0;
    for (; j + 1 < deg; j += 2) {
        int s0 = g_ssrc[beg + j];
        int s1 = g_ssrc[beg + j + 1];
        float e0 = (j < DEG_CAP) ? sc[wIn][j] : g_score[beg + j];
        float e1 = (j + 1 < DEG_CAP) ? sc[wIn][j + 1] : g_score[beg + j + 1];
        float al0 = e0 * rden, al1 = e1 * rden;
        const float* v0p = g_v + (size_t)s0 * d;
        const float* v1p = g_v + (size_t)s1 * d;
        float4 b0 = *(const float4*)(v0p + lane * 4);
        float4 c0 = *(const float4*)(v1p + lane * 4);
        a0.x += al0 * b0.x + al1 * c0.x;
        a0.y += al0 * b0.y + al1 * c0.y;
        a0.z += al0 * b0.z + al1 * c0.z;
        a0.w += al0 * b0.w + al1 * c0.w;
        if (nv > 1) {
            float4 b1 = *(const float4*)(v0p + 128 + lane * 4);
            float4 c1 = *(const float4*)(v1p + 128 + lane * 4);
            a1.x += al0 * b1.x + al1 * c1.x;
            a1.y += al0 * b1.y + al1 * c1.y;
            a1.z += al0 * b1.z + al1 * c1.z;
            a1.w += al0 * b1.w + al1 * c1.w;
        }
    }
    if (j < deg) {
        int s = g_ssrc[beg + j];
        float e = (j < DEG_CAP) ? sc[wIn][j] : g_score[beg + j];
        float alpha = e * rden;
        const float* vr = g_v + (size_t)s * d;
        float4 b0 = *(const float4*)(vr + lane * 4);
        a0.x += alpha * b0.x; a0.y += alpha * b0.y;
        a0.z += alpha * b0.z; a0.w += alpha * b0.w;
        if (nv > 1) {
            float4 b1 = *(const float4*)(vr + 128 + lane * 4);
            a1.x += alpha * b1.x; a1.y += alpha * b1.y;
            a1.z += alpha * b1.z; a1.w += alpha * b1.w;
        }
    }

    float* hr = sel(h_sel) + (size_t)gw * d;
    float4 h0 = *(float4*)(hr + lane * 4);
    h0.x += a0.x; h0.y += a0.y; h0.z += a0.z; h0.w += a0.w;
    *(float4*)(hr + lane * 4) = h0;
    if (nv > 1) {
        float4 h1 = *(float4*)(hr + 128 + lane * 4);
        h1.x += a1.x; h1.y += a1.y; h1.z += a1.z; h1.w += a1.w;
        *(float4*)(hr + 128 + lane * 4) = h1;
    }
}

// ---------------- pooling ----------------
__global__ void pool_init_kernel() {
    int c = threadIdx.x;
    if (c < 256) {
        g_psum[c] = 0.f;
        g_pmax[c] = ENC_NEG_INF;
    }
}

__global__ void pool_kernel(int M, int d) {
    int c = threadIdx.x;
    const float* h = g_h2;
    float sum = 0.f, mx = -FLT_MAX;
    for (int r = blockIdx.x; r < M; r += gridDim.x) {
        float v = h[(size_t)r * d + c];
        sum += v;
        mx = fmaxf(mx, v);
    }
    atomicAdd(&g_psum[c], sum);
    atomicMax(&g_pmax[c], fenc(mx));
}

__global__ void pool_final_kernel(float* __restrict__ out, int M, int d) {
    int c = threadIdx.x;
    if (c < d) {
        out[c] = g_psum[c] / (float)M;
        out[d + c] = fdec(g_pmax[c]);
    }
}

// ---------------- launch ----------------
extern "C" void kernel_launch(void* const* d_in, const int* in_sizes, int n_in,
                              void* d_out, int out_size) {
    const float* x   = (const float*)d_in[0];
    const void*  ei  = d_in[1];
    const float* Wq1 = (const float*)d_in[3];
    const float* bq1 = (const float*)d_in[4];
    const float* Wk1 = (const float*)d_in[5];
    const float* bk1 = (const float*)d_in[6];
    const float* Wv1 = (const float*)d_in[7];
    const float* bv1 = (const float*)d_in[8];
    const float* Ws1 = (const float*)d_in[9];
    const float* bs1 = (const float*)d_in[10];
    const float* Wq2 = (const float*)d_in[11];
    const float* bq2 = (const float*)d_in[12];
    const float* Wk2 = (const float*)d_in[13];
    const float* bk2 = (const float*)d_in[14];
    const float* Wv2 = (const float*)d_in[15];
    const float* bv2 = (const float*)d_in[16];
    const float* Ws2 = (const float*)d_in[17];
    const float* bs2 = (const float*)d_in[18];
    float* out = (float*)d_out;

    const int D_IN = 512, D_HID = 256, D_OUT = 128;
    int Nn = in_sizes[0] / D_IN;
    int E  = in_sizes[2];

    static int smem_set = 0;
    if (!smem_set) {
        cudaFuncSetAttribute(gemm_mma_kernel,
                             cudaFuncAttributeMaxDynamicSharedMemorySize, GEMM_SMEM);
        smem_set = 1;
    }

    // ---- graph preprocessing: CSR by dst ----
    int nb = (Nn + 255) / 256;
    detect_kernel<<<1, 32>>>((const unsigned*)ei, E);
    zero_deg_kernel<<<nb, 256>>>(Nn);
    convert_kernel<<<(E + 255) / 256, 256>>>(ei, E);
    part_sum_kernel<<<nb, 256>>>(Nn);
    part_scan_kernel<<<1, 256>>>(nb, Nn);
    off_kernel<<<nb, 256>>>(Nn);
    permute_kernel<<<(E + 255) / 256, 256>>>(E);

    // ---- weight pre-split (both layers, once) ----
    {
        dim3 g1((D_IN * D_HID + 255) / 256, 4);
        split_w_kernel<<<g1, 256>>>(Wq1, Wk1, Wv1, Ws1, D_IN, D_HID, 0);
        dim3 g2((D_HID * D_OUT + 255) / 256, 4);
        split_w_kernel<<<g2, 256>>>(Wq2, Wk2, Wv2, Ws2, D_HID, D_OUT, WOFF_L2);
    }

    int nTiles = (Nn + 127) / 128;
    int edgeBlks = (Nn * 32 + 255) / 256;

    // ===== layer 1 =====
    {
        int t4 = Nn * D_IN / 4;
        split_a_kernel<<<(t4 + 255) / 256, 256>>>(x, -1, t4, 1);
        dim3 g(8, nTiles);
        gemm_mma_kernel<<<g, 256, GEMM_SMEM>>>(
            0, bq1, bk1, bv1, bs1, 0, 1, 2, 3, Nn, D_IN, D_HID);
    }
    edge_fused_kernel<<<edgeBlks, 256>>>(Nn, D_HID, 3,
        (float)(1.0 / sqrt((double)D_HID)));

    // ===== layer 2 =====
    {
        int t4 = Nn * D_HID / 4;
        split_a_kernel<<<(t4 + 255) / 256, 256>>>(nullptr, 3, t4, 0);
        dim3 g(4, nTiles);
        gemm_mma_kernel<<<g, 256, GEMM_SMEM>>>(
            WOFF_L2, bq2, bk2, bv2, bs2, 0, 1, 2, 4, Nn, D_HID, D_OUT);
    }
    edge_fused_kernel<<<edgeBlks, 256>>>(Nn, D_OUT, 4,
        (float)(1.0 / sqrt((double)D_OUT)));

    // ===== pooling =====
    pool_init_kernel<<<1, 256>>>();
    pool_kernel<<<256, D_OUT>>>(Nn, D_OUT);
    pool_final_kernel<<<1, 256>>>(out, Nn, D_OUT);
}

// round 10
// speedup vs baseline: 3.6359x; 1.1242x over previous
#include <cuda_runtime.h>
#include <cuda_bf16.h>
#include <math.h>
#include <float.h>
#include <stdint.h>

#define MAXN 50000
#define MAXE 800000
#define DMAX 256
#define DEG_CAP 64

// ---------------- static device scratch ----------------
__device__ float g_q[(size_t)MAXN * DMAX];
__device__ float g_k[(size_t)MAXN * DMAX];
__device__ float g_v[(size_t)MAXN * DMAX];
__device__ float g_h1[(size_t)MAXN * DMAX];
__device__ float g_h2[(size_t)MAXN * DMAX];
__device__ float g_score[MAXE];
__device__ int g_src[MAXE];
__device__ int g_dst[MAXE];
__device__ int g_ssrc[MAXE];
__device__ int g_deg[MAXN];
__device__ int g_off[MAXN + 1];
__device__ int g_cursor[MAXN];
__device__ int g_part[256];
__device__ int g_is64;
__device__ float g_psum[256];
__device__ unsigned g_pmax[256];

// pre-split bf16 operands (16B-aligned via uint4 backing)
__device__ uint4 g_ah4[(size_t)MAXN * 512 / 8];   // A hi
__device__ uint4 g_al4[(size_t)MAXN * 512 / 8];   // A lo
__device__ uint4 g_wh4[81920];                     // W hi
__device__ uint4 g_wl4[81920];                     // W lo
#define WOFF_L2 524288

__device__ __forceinline__ float* sel(int w) {
    switch (w) {
        case 0: return g_q;
        case 1: return g_k;
        case 2: return g_v;
        case 3: return g_h1;
        default: return g_h2;
    }
}

__device__ __forceinline__ unsigned fenc(float f) {
    unsigned u = __float_as_uint(f);
    return (u & 0x80000000u) ? ~u : (u | 0x80000000u);
}
__device__ __forceinline__ float fdec(unsigned u) {
    u = (u & 0x80000000u) ? (u ^ 0x80000000u) : ~u;
    return __uint_as_float(u);
}
#define ENC_NEG_INF 0x007FFFFFu

// ---------------- PTX helpers ----------------
__device__ __forceinline__ uint32_t smem_u32(const void* p) {
    uint32_t a;
    asm("{ .reg .u64 t; cvta.to.shared.u64 t, %1; cvt.u32.u64 %0, t; }" : "=r"(a) : "l"(p));
    return a;
}

__device__ __forceinline__ void ldm_x4(uint32_t& r0, uint32_t& r1, uint32_t& r2, uint32_t& r3,
                                       uint32_t addr) {
    asm volatile("ldmatrix.sync.aligned.m8n8.x4.shared.b16 {%0,%1,%2,%3}, [%4];"
        : "=r"(r0), "=r"(r1), "=r"(r2), "=r"(r3) : "r"(addr));
}

__device__ __forceinline__ void mma_bf16(float* c, const uint32_t* a, const uint32_t* b) {
    asm volatile("mma.sync.aligned.m16n8k16.row.col.f32.bf16.bf16.f32 "
        "{%0,%1,%2,%3}, {%4,%5,%6,%7}, {%8,%9}, {%0,%1,%2,%3};"
        : "+f"(c[0]), "+f"(c[1]), "+f"(c[2]), "+f"(c[3])
        : "r"(a[0]), "r"(a[1]), "r"(a[2]), "r"(a[3]), "r"(b[0]), "r"(b[1]));
}

__device__ __forceinline__ void cp16(uint32_t saddr, const void* gptr, int srcsize) {
    asm volatile("cp.async.ca.shared.global [%0], [%1], 16, %2;"
        :: "r"(saddr), "l"(gptr), "r"(srcsize) : "memory");
}
__device__ __forceinline__ void cp_commit() {
    asm volatile("cp.async.commit_group;" ::: "memory");
}
__device__ __forceinline__ void cp_wait0() {
    asm volatile("cp.async.wait_group 0;" ::: "memory");
}
__device__ __forceinline__ void cp_wait1() {
    asm volatile("cp.async.wait_group 1;" ::: "memory");
}

__device__ __forceinline__ uint32_t pack_bf(float a, float b) {
    __nv_bfloat162 t = __floats2bfloat162_rn(a, b);
    return *(uint32_t*)&t;
}
__device__ __forceinline__ float bf_hi_val(float v, float& lo) {
    __nv_bfloat16 h = __float2bfloat16_rn(v);
    float hf = __bfloat162float(h);
    lo = v - hf;
    return hf;
}

// ---------------- graph preprocessing ----------------
__global__ void detect_kernel(const unsigned* __restrict__ ei, int E) {
    if (threadIdx.x == 0 && blockIdx.x == 0) {
        int n = E < 64 ? E : 64;
        int is64 = 1;
        for (int i = 0; i < n; i++) {
            if (ei[2 * i + 1] != 0u) { is64 = 0; break; }
        }
        g_is64 = is64;
    }
}

__global__ void zero_deg_kernel(int Nn) {
    int i = blockIdx.x * blockDim.x + threadIdx.x;
    if (i < Nn) g_deg[i] = 0;
}

__global__ void convert_kernel(const void* __restrict__ ei, int E) {
    int i = blockIdx.x * blockDim.x + threadIdx.x;
    if (i >= E) return;
    int s, t;
    if (g_is64) {
        const long long* p = (const long long*)ei;
        s = (int)p[i];
        t = (int)p[E + i];
    } else {
        const int* p = (const int*)ei;
        s = p[i];
        t = p[E + i];
    }
    g_src[i] = s;
    g_dst[i] = t;
    atomicAdd(&g_deg[t], 1);
}

__global__ void part_sum_kernel(int Nn) {
    __shared__ int red[256];
    int t = threadIdx.x;
    int i = blockIdx.x * 256 + t;
    red[t] = (i < Nn) ? g_deg[i] : 0;
    __syncthreads();
    for (int o = 128; o; o >>= 1) {
        if (t < o) red[t] += red[t + o];
        __syncthreads();
    }
    if (t == 0) g_part[blockIdx.x] = red[0];
}

__global__ void part_scan_kernel(int nb, int Nn) {
    __shared__ int s[256];
    int t = threadIdx.x;
    s[t] = (t < nb) ? g_part[t] : 0;
    __syncthreads();
    for (int o = 1; o < 256; o <<= 1) {
        int u = (t >= o) ? s[t - o] : 0;
        __syncthreads();
        s[t] += u;
        __syncthreads();
    }
    g_part[t] = (t > 0) ? s[t - 1] : 0;
    if (t == 255) g_off[Nn] = s[255];
}

__global__ void off_kernel(int Nn) {
    __shared__ int s[256];
    int t = threadIdx.x;
    int i = blockIdx.x * 256 + t;
    int v = (i < Nn) ? g_deg[i] : 0;
    s[t] = v;
    __syncthreads();
    for (int o = 1; o < 256; o <<= 1) {
        int u = (t >= o) ? s[t - o] : 0;
        __syncthreads();
        s[t] += u;
        __syncthreads();
    }
    if (i < Nn) {
        int excl = s[t] - v + g_part[blockIdx.x];
        g_off[i] = excl;
        g_cursor[i] = excl;
    }
}

__global__ void permute_kernel(int E) {
    int i = blockIdx.x * blockDim.x + threadIdx.x;
    if (i >= E) return;
    int t = g_dst[i];
    int pos = atomicAdd(&g_cursor[t], 1);
    g_ssrc[pos] = g_src[i];
}

// ---------------- operand pre-splitting ----------------
__global__ void split_a_kernel(const float* __restrict__ Aext, int a_sel,
                               int total4, int sanitize) {
    int i = blockIdx.x * blockDim.x + threadIdx.x;
    if (i >= total4) return;
    const float* A = (a_sel >= 0) ? sel(a_sel) : Aext;
    float4 v = ((const float4*)A)[i];
    if (sanitize) {
        if (v.x != v.x) v.x = 0.f;
        if (v.y != v.y) v.y = 0.f;
        if (v.z != v.z) v.z = 0.f;
        if (v.w != v.w) v.w = 0.f;
    }
    float lx, ly, lz, lw;
    float hx = bf_hi_val(v.x, lx);
    float hy = bf_hi_val(v.y, ly);
    float hz = bf_hi_val(v.z, lz);
    float hw = bf_hi_val(v.w, lw);
    ((uint2*)g_ah4)[i] = make_uint2(pack_bf(hx, hy), pack_bf(hz, hw));
    ((uint2*)g_al4)[i] = make_uint2(pack_bf(lx, ly), pack_bf(lz, lw));
}

__global__ void split_w_kernel(const float* __restrict__ W0, const float* __restrict__ W1,
                               const float* __restrict__ W2, const float* __restrict__ W3,
                               int K, int Nt, int base) {
    int i = blockIdx.x * blockDim.x + threadIdx.x;
    if (i >= K * Nt) return;
    int w = blockIdx.y;
    const float* W = (w == 0) ? W0 : (w == 1) ? W1 : (w == 2) ? W2 : W3;
    int k = i / Nt, n = i - k * Nt;
    float v = W[i];
    float lo;
    float hi = bf_hi_val(v, lo);
    size_t o = (size_t)base + (size_t)w * K * Nt + (size_t)n * K + k;
    ((__nv_bfloat16*)g_wh4)[o] = __float2bfloat16_rn(hi);
    ((__nv_bfloat16*)g_wl4)[o] = __float2bfloat16_rn(lo);
}

// ================= bf16 mma.sync GEMM, cp.async pipeline, occ 2 =================
#define OFF_AH 0
#define OFF_AL 10240
#define OFF_BH 20480
#define OFF_BL 30720
#define BUF_SZ 40960
#define GEMM_SMEM (2 * BUF_SZ)

__global__ __launch_bounds__(256, 2)
void gemm_mma_kernel(int wbase,
                     const float* __restrict__ b0, const float* __restrict__ b1,
                     const float* __restrict__ b2, const float* __restrict__ b3,
                     int c0, int c1, int c2, int c3,
                     int M, int K, int Nt) {
    extern __shared__ char smem[];
    const uint32_t sbase = smem_u32(smem);

    const int tid = threadIdx.x;
    const int wid = tid >> 5;
    const int lid = tid & 31;
    const int wm = wid & 1;
    const int wn = wid >> 1;
    const int rowBase = blockIdx.y * 128;

    const int cbPerW = Nt >> 7;
    const int wsel = blockIdx.x / cbPerW;
    const int colBase = (blockIdx.x - wsel * cbPerW) * 128;

    const __nv_bfloat16* Ah = (const __nv_bfloat16*)g_ah4;
    const __nv_bfloat16* Al = (const __nv_bfloat16*)g_al4;
    const __nv_bfloat16* Wh = (const __nv_bfloat16*)g_wh4 + (size_t)wbase + (size_t)wsel * K * Nt;
    const __nv_bfloat16* Wl = (const __nv_bfloat16*)g_wl4 + (size_t)wbase + (size_t)wsel * K * Nt;

    const float* bias;
    int csel;
    switch (wsel) {
        case 0: bias = b0; csel = c0; break;
        case 1: bias = b1; csel = c1; break;
        case 2: bias = b2; csel = c2; break;
        default: bias = b3; csel = c3; break;
    }
    float* C = sel(csel);

    float acc[4][4][4];
#pragma unroll
    for (int i = 0; i < 4; i++)
#pragma unroll
        for (int j = 0; j < 4; j++)
#pragma unroll
            for (int q = 0; q < 4; q++) acc[i][j][q] = 0.f;

    // copy mapping: idx = tid + i*256 in [0,512): row = idx>>2 (0..127), kq = idx&3 (8 bf16 = 16B)
    const int l_row = tid >> 2;
    const int l_kq = tid & 3;
    const int nChunks = K >> 5;

    // per-thread source pointers
    const int grow0 = rowBase + l_row;
    const int grow1 = rowBase + l_row + 64;
    const int a_ok0 = (grow0 < M) ? 16 : 0;
    const int a_ok1 = (grow1 < M) ? 16 : 0;
    const int n0 = colBase + l_row;
    const int n1 = colBase + l_row + 64;
    const uint32_t soff0 = (uint32_t)(l_row * 80 + l_kq * 16);
    const uint32_t soff1 = soff0 + 64 * 80;

    // issue chunk copies into buffer b
    auto issue = [&](int c, int b) {
        const int k0 = c << 5;
        uint32_t bb = sbase + b * BUF_SZ;
        cp16(bb + OFF_AH + soff0, Ah + (size_t)grow0 * K + k0 + l_kq * 8, a_ok0);
        cp16(bb + OFF_AL + soff0, Al + (size_t)grow0 * K + k0 + l_kq * 8, a_ok0);
        cp16(bb + OFF_AH + soff1, Ah + (size_t)grow1 * K + k0 + l_kq * 8, a_ok1);
        cp16(bb + OFF_AL + soff1, Al + (size_t)grow1 * K + k0 + l_kq * 8, a_ok1);
        cp16(bb + OFF_BH + soff0, Wh + (size_t)n0 * K + k0 + l_kq * 8, 16);
        cp16(bb + OFF_BL + soff0, Wl + (size_t)n0 * K + k0 + l_kq * 8, 16);
        cp16(bb + OFF_BH + soff1, Wh + (size_t)n1 * K + k0 + l_kq * 8, 16);
        cp16(bb + OFF_BL + soff1, Wl + (size_t)n1 * K + k0 + l_kq * 8, 16);
        cp_commit();
    };

    issue(0, 0);

    int buf = 0;
    for (int c = 0; c < nChunks; c++) {
        if (c + 1 < nChunks) {
            issue(c + 1, buf ^ 1);
            cp_wait1();
        } else {
            cp_wait0();
        }
        __syncthreads();

        uint32_t bb = sbase + buf * BUF_SZ;
        const int lr = lid & 15;
        const int lc = lid >> 4;
        uint32_t AHB = bb + OFF_AH, ALB = bb + OFF_AL;
        uint32_t BHB = bb + OFF_BH, BLB = bb + OFF_BL;
#pragma unroll
        for (int ks = 0; ks < 2; ks++) {
            uint32_t koff = (uint32_t)(ks * 32 + lc * 16);
            uint32_t ah[4][4], al[4][4], bh[4][2], bl[4][2];
#pragma unroll
            for (int i = 0; i < 4; i++) {
                uint32_t ro = (uint32_t)((wm * 64 + i * 16 + lr) * 80) + koff;
                ldm_x4(ah[i][0], ah[i][1], ah[i][2], ah[i][3], AHB + ro);
                ldm_x4(al[i][0], al[i][1], al[i][2], al[i][3], ALB + ro);
            }
#pragma unroll
            for (int j2 = 0; j2 < 2; j2++) {
                uint32_t ro = (uint32_t)((wn * 32 + j2 * 16 + lr) * 80) + koff;
                uint32_t r0, r1, r2, r3;
                ldm_x4(r0, r1, r2, r3, BHB + ro);
                bh[j2 * 2 + 0][0] = r0; bh[j2 * 2 + 0][1] = r2;
                bh[j2 * 2 + 1][0] = r1; bh[j2 * 2 + 1][1] = r3;
                ldm_x4(r0, r1, r2, r3, BLB + ro);
                bl[j2 * 2 + 0][0] = r0; bl[j2 * 2 + 0][1] = r2;
                bl[j2 * 2 + 1][0] = r1; bl[j2 * 2 + 1][1] = r3;
            }
#pragma unroll
            for (int i = 0; i < 4; i++)
#pragma unroll
                for (int j = 0; j < 4; j++) {
                    mma_bf16(acc[i][j], ah[i], bh[j]);
                    mma_bf16(acc[i][j], ah[i], bl[j]);
                    mma_bf16(acc[i][j], al[i], bh[j]);
                }
        }
        __syncthreads();
        buf ^= 1;
    }

    const int lr4 = lid >> 2;
    const int lc2 = (lid & 3) * 2;
#pragma unroll
    for (int j = 0; j < 4; j++) {
        int gc = colBase + wn * 32 + j * 8 + lc2;
        float bi0 = bias[gc], bi1 = bias[gc + 1];
#pragma unroll
        for (int i = 0; i < 4; i++) {
            int gr0 = rowBase + wm * 64 + i * 16 + lr4;
            int gr1 = gr0 + 8;
            if (gr0 < M) {
                float2 o = make_float2(acc[i][j][0] + bi0, acc[i][j][1] + bi1);
                *(float2*)(C + (size_t)gr0 * Nt + gc) = o;
            }
            if (gr1 < M) {
                float2 o = make_float2(acc[i][j][2] + bi0, acc[i][j][3] + bi1);
                *(float2*)(C + (size_t)gr1 * Nt + gc) = o;
            }
        }
    }
}

// ================= fused per-node edge kernel (2-edge pipelined) =================
// do_split: also emit bf16 hi/lo of the final h row into g_ah4/g_al4 (layer-1 only, d=256)
__global__ __launch_bounds__(256)
void edge_fused_kernel(int Nn, int d, int h_sel, float inv_sqrt_d, int do_split) {
    __shared__ float sc[8][DEG_CAP];
    int gw = (blockIdx.x * blockDim.x + threadIdx.x) >> 5;
    int lane = threadIdx.x & 31;
    int wIn = threadIdx.x >> 5;
    if (gw >= Nn) return;
    int beg = g_off[gw];
    int deg = g_off[gw + 1] - beg;

    const int nv = d >> 7;
    float4 a0 = make_float4(0.f, 0.f, 0.f, 0.f);
    float4 a1 = make_float4(0.f, 0.f, 0.f, 0.f);

    if (deg > 0) {
        const float* qr = g_q + (size_t)gw * d;
        float4 q0 = *(const float4*)(qr + lane * 4);
        float4 q1 = make_float4(0.f, 0.f, 0.f, 0.f);
        if (nv > 1) q1 = *(const float4*)(qr + 128 + lane * 4);

        float mx = -FLT_MAX;
        int j = 0;
        for (; j + 1 < deg; j += 2) {
            int s0 = g_ssrc[beg + j];
            int s1 = g_ssrc[beg + j + 1];
            const float* k0p = g_k + (size_t)s0 * d;
            const float* k1p = g_k + (size_t)s1 * d;
            float4 b0 = *(const float4*)(k0p + lane * 4);
            float4 c0 = *(const float4*)(k1p + lane * 4);
            float sa = q0.x * b0.x + q0.y * b0.y + q0.z * b0.z + q0.w * b0.w;
            float sb = q0.x * c0.x + q0.y * c0.y + q0.z * c0.z + q0.w * c0.w;
            if (nv > 1) {
                float4 b1 = *(const float4*)(k0p + 128 + lane * 4);
                float4 c1 = *(const float4*)(k1p + 128 + lane * 4);
                sa += q1.x * b1.x + q1.y * b1.y + q1.z * b1.z + q1.w * b1.w;
                sb += q1.x * c1.x + q1.y * c1.y + q1.z * c1.z + q1.w * c1.w;
            }
#pragma unroll
            for (int o = 16; o; o >>= 1) {
                sa += __shfl_xor_sync(0xFFFFFFFFu, sa, o);
                sb += __shfl_xor_sync(0xFFFFFFFFu, sb, o);
            }
            sa *= inv_sqrt_d;
            sb *= inv_sqrt_d;
            mx = fmaxf(mx, fmaxf(sa, sb));
            if (lane == 0) {
                if (j < DEG_CAP) sc[wIn][j] = sa; else g_score[beg + j] = sa;
                if (j + 1 < DEG_CAP) sc[wIn][j + 1] = sb; else g_score[beg + j + 1] = sb;
            }
        }
        if (j < deg) {
            int s = g_ssrc[beg + j];
            const float* kr = g_k + (size_t)s * d;
            float4 b0 = *(const float4*)(kr + lane * 4);
            float sum = q0.x * b0.x + q0.y * b0.y + q0.z * b0.z + q0.w * b0.w;
            if (nv > 1) {
                float4 b1 = *(const float4*)(kr + 128 + lane * 4);
                sum += q1.x * b1.x + q1.y * b1.y + q1.z * b1.z + q1.w * b1.w;
            }
#pragma unroll
            for (int o = 16; o; o >>= 1) sum += __shfl_xor_sync(0xFFFFFFFFu, sum, o);
            sum *= inv_sqrt_d;
            mx = fmaxf(mx, sum);
            if (lane == 0) {
                if (j < DEG_CAP) sc[wIn][j] = sum; else g_score[beg + j] = sum;
            }
        }
        __syncwarp();

        float den = 0.f;
        for (int jj = lane; jj < deg; jj += 32) {
            float v = (jj < DEG_CAP) ? sc[wIn][jj] : g_score[beg + jj];
            float e = expf(v - mx);
            if (jj < DEG_CAP) sc[wIn][jj] = e;
            else g_score[beg + jj] = e;
            den += e;
        }
#pragma unroll
        for (int o = 16; o; o >>= 1) den += __shfl_xor_sync(0xFFFFFFFFu, den, o);
        float rden = 1.f / den;
        __syncwarp();

        j = 0;
        for (; j + 1 < deg; j += 2) {
            int s0 = g_ssrc[beg + j];
            int s1 = g_ssrc[beg + j + 1];
            float e0 = (j < DEG_CAP) ? sc[wIn][j] : g_score[beg + j];
            float e1 = (j + 1 < DEG_CAP) ? sc[wIn][j + 1] : g_score[beg + j + 1];
            float al0 = e0 * rden, al1 = e1 * rden;
            const float* v0p = g_v + (size_t)s0 * d;
            const float* v1p = g_v + (size_t)s1 * d;
            float4 b0 = *(const float4*)(v0p + lane * 4);
            float4 c0 = *(const float4*)(v1p + lane * 4);
            a0.x += al0 * b0.x + al1 * c0.x;
            a0.y += al0 * b0.y + al1 * c0.y;
            a0.z += al0 * b0.z + al1 * c0.z;
            a0.w += al0 * b0.w + al1 * c0.w;
            if (nv > 1) {
                float4 b1 = *(const float4*)(v0p + 128 + lane * 4);
                float4 c1 = *(const float4*)(v1p + 128 + lane * 4);
                a1.x += al0 * b1.x + al1 * c1.x;
                a1.y += al0 * b1.y + al1 * c1.y;
                a1.z += al0 * b1.z + al1 * c1.z;
                a1.w += al0 * b1.w + al1 * c1.w;
            }
        }
        if (j < deg) {
            int s = g_ssrc[beg + j];
            float e = (j < DEG_CAP) ? sc[wIn][j] : g_score[beg + j];
            float alpha = e * rden;
            const float* vr = g_v + (size_t)s * d;
            float4 b0 = *(const float4*)(vr + lane * 4);
            a0.x += alpha * b0.x; a0.y += alpha * b0.y;
            a0.z += alpha * b0.z; a0.w += alpha * b0.w;
            if (nv > 1) {
                float4 b1 = *(const float4*)(vr + 128 + lane * 4);
                a1.x += alpha * b1.x; a1.y += alpha * b1.y;
                a1.z += alpha * b1.z; a1.w += alpha * b1.w;
            }
        }
    }

    float* hr = sel(h_sel) + (size_t)gw * d;
    float4 h0 = *(float4*)(hr + lane * 4);
    h0.x += a0.x; h0.y += a0.y; h0.z += a0.z; h0.w += a0.w;
    *(float4*)(hr + lane * 4) = h0;
    float4 h1 = make_float4(0.f, 0.f, 0.f, 0.f);
    if (nv > 1) {
        h1 = *(float4*)(hr + 128 + lane * 4);
        h1.x += a1.x; h1.y += a1.y; h1.z += a1.z; h1.w += a1.w;
        *(float4*)(hr + 128 + lane * 4) = h1;
    }

    // fused bf16 hi/lo split of the final h row (feeds layer-2 GEMM)
    if (do_split) {
        __nv_bfloat16* AhP = (__nv_bfloat16*)g_ah4;
        __nv_bfloat16* AlP = (__nv_bfloat16*)g_al4;
        float lx, ly, lz, lw;
        float hx = bf_hi_val(h0.x, lx);
        float hy = bf_hi_val(h0.y, ly);
        float hz = bf_hi_val(h0.z, lz);
        float hw = bf_hi_val(h0.w, lw);
        *(uint2*)(AhP + (size_t)gw * d + lane * 4) = make_uint2(pack_bf(hx, hy), pack_bf(hz, hw));
        *(uint2*)(AlP + (size_t)gw * d + lane * 4) = make_uint2(pack_bf(lx, ly), pack_bf(lz, lw));
        if (nv > 1) {
            float hx1 = bf_hi_val(h1.x, lx);
            float hy1 = bf_hi_val(h1.y, ly);
            float hz1 = bf_hi_val(h1.z, lz);
            float hw1 = bf_hi_val(h1.w, lw);
            *(uint2*)(AhP + (size_t)gw * d + 128 + lane * 4) = make_uint2(pack_bf(hx1, hy1), pack_bf(hz1, hw1));
            *(uint2*)(AlP + (size_t)gw * d + 128 + lane * 4) = make_uint2(pack_bf(lx, ly), pack_bf(lz, lw));
        }
    }
}

// ---------------- pooling ----------------
__global__ void pool_init_kernel() {
    int c = threadIdx.x;
    if (c < 256) {
        g_psum[c] = 0.f;
        g_pmax[c] = ENC_NEG_INF;
    }
}

__global__ void pool_kernel(int M, int d) {
    int c = threadIdx.x;
    const float* h = g_h2;
    float sum = 0.f, mx = -FLT_MAX;
    for (int r = blockIdx.x; r < M; r += gridDim.x) {
        float v = h[(size_t)r * d + c];
        sum += v;
        mx = fmaxf(mx, v);
    }
    atomicAdd(&g_psum[c], sum);
    atomicMax(&g_pmax[c], fenc(mx));
}

__global__ void pool_final_kernel(float* __restrict__ out, int M, int d) {
    int c = threadIdx.x;
    if (c < d) {
        out[c] = g_psum[c] / (float)M;
        out[d + c] = fdec(g_pmax[c]);
    }
}

// ---------------- launch ----------------
extern "C" void kernel_launch(void* const* d_in, const int* in_sizes, int n_in,
                              void* d_out, int out_size) {
    const float* x   = (const float*)d_in[0];
    const void*  ei  = d_in[1];
    const float* Wq1 = (const float*)d_in[3];
    const float* bq1 = (const float*)d_in[4];
    const float* Wk1 = (const float*)d_in[5];
    const float* bk1 = (const float*)d_in[6];
    const float* Wv1 = (const float*)d_in[7];
    const float* bv1 = (const float*)d_in[8];
    const float* Ws1 = (const float*)d_in[9];
    const float* bs1 = (const float*)d_in[10];
    const float* Wq2 = (const float*)d_in[11];
    const float* bq2 = (const float*)d_in[12];
    const float* Wk2 = (const float*)d_in[13];
    const float* bk2 = (const float*)d_in[14];
    const float* Wv2 = (const float*)d_in[15];
    const float* bv2 = (const float*)d_in[16];
    const float* Ws2 = (const float*)d_in[17];
    const float* bs2 = (const float*)d_in[18];
    float* out = (float*)d_out;

    const int D_IN = 512, D_HID = 256, D_OUT = 128;
    int Nn = in_sizes[0] / D_IN;
    int E  = in_sizes[2];

    static int smem_set = 0;
    if (!smem_set) {
        cudaFuncSetAttribute(gemm_mma_kernel,
                             cudaFuncAttributeMaxDynamicSharedMemorySize, GEMM_SMEM);
        smem_set = 1;
    }

    // ---- graph preprocessing: CSR by dst ----
    int nb = (Nn + 255) / 256;
    detect_kernel<<<1, 32>>>((const unsigned*)ei, E);
    zero_deg_kernel<<<nb, 256>>>(Nn);
    convert_kernel<<<(E + 255) / 256, 256>>>(ei, E);
    part_sum_kernel<<<nb, 256>>>(Nn);
    part_scan_kernel<<<1, 256>>>(nb, Nn);
    off_kernel<<<nb, 256>>>(Nn);
    permute_kernel<<<(E + 255) / 256, 256>>>(E);

    // ---- weight pre-split (both layers, once) ----
    {
        dim3 g1((D_IN * D_HID + 255) / 256, 4);
        split_w_kernel<<<g1, 256>>>(Wq1, Wk1, Wv1, Ws1, D_IN, D_HID, 0);
        dim3 g2((D_HID * D_OUT + 255) / 256, 4);
        split_w_kernel<<<g2, 256>>>(Wq2, Wk2, Wv2, Ws2, D_HID, D_OUT, WOFF_L2);
    }

    int nTiles = (Nn + 127) / 128;
    int edgeBlks = (Nn * 32 + 255) / 256;

    // ===== layer 1 =====
    {
        int t4 = Nn * D_IN / 4;
        split_a_kernel<<<(t4 + 255) / 256, 256>>>(x, -1, t4, 1);
        dim3 g(8, nTiles);
        gemm_mma_kernel<<<g, 256, GEMM_SMEM>>>(
            0, bq1, bk1, bv1, bs1, 0, 1, 2, 3, Nn, D_IN, D_HID);
    }
    edge_fused_kernel<<<edgeBlks, 256>>>(Nn, D_HID, 3,
        (float)(1.0 / sqrt((double)D_HID)), 1);

    // ===== layer 2 (A split produced by layer-1 edge kernel) =====
    {
        dim3 g(4, nTiles);
        gemm_mma_kernel<<<g, 256, GEMM_SMEM>>>(
            WOFF_L2, bq2, bk2, bv2, bs2, 0, 1, 2, 4, Nn, D_HID, D_OUT);
    }
    edge_fused_kernel<<<edgeBlks, 256>>>(Nn, D_OUT, 4,
        (float)(1.0 / sqrt((double)D_OUT)), 0);

    // ===== pooling =====
    pool_init_kernel<<<1, 256>>>();
    pool_kernel<<<256, D_OUT>>>(Nn, D_OUT);
    pool_final_kernel<<<1, 256>>>(out, Nn, D_OUT);
}